// round 1
// baseline (speedup 1.0000x reference)
#include <cuda_runtime.h>
#include <math.h>

// Problem constants
#define B_ 2
#define T_ 2048
#define C_ 2048
#define H_ 16
#define D_ 128
#define M_ (B_ * T_)          // 4096 rows for all projections
#define ND_ (H_ * D_)         // 2048

// ---------------------------------------------------------------------------
// Scratch (no allocations allowed -> __device__ globals)
// ---------------------------------------------------------------------------
__device__ float g_q[(size_t)B_ * H_ * T_ * D_];   // (B,H,T,D)
__device__ float g_k[(size_t)B_ * H_ * T_ * D_];
__device__ float g_v[(size_t)B_ * H_ * T_ * D_];
__device__ float g_ao[(size_t)B_ * T_ * C_];       // attention out, (B,T,H*D)
__device__ float g_cos[T_ * (D_ / 2)];
__device__ float g_sin[T_ * (D_ / 2)];

// ---------------------------------------------------------------------------
// RoPE table
// ---------------------------------------------------------------------------
__global__ void rope_table_kernel() {
    int i = blockIdx.x * blockDim.x + threadIdx.x;
    if (i >= T_ * (D_ / 2)) return;
    int t  = i >> 6;          // D_/2 = 64
    int d2 = i & 63;
    float inv = powf(10000.0f, -((float)(2 * d2)) / (float)D_);
    float ang = (float)t * inv;
    g_cos[i] = cosf(ang);
    g_sin[i] = sinf(ang);
}

// ---------------------------------------------------------------------------
// SGEMM 128x128x8, 256 threads, 8x8 per thread.
// OP: 0 -> Q proj (RoPE, store (B,H,T,D) to g_q)
//     1 -> K proj (RoPE, store (B,H,T,D) to g_k)
//     2 -> V proj (store (B,H,T,D) to g_v)
//     3 -> out proj (A = g_ao, plain row-major store to Cparam)
// ---------------------------------------------------------------------------
template <int OP>
__global__ void __launch_bounds__(256, 2)
gemm128_kernel(const float* __restrict__ Aparam,
               const float* __restrict__ W,
               float* __restrict__ Cparam) {
    constexpr int Kdim = C_;    // 2048
    constexpr int Ndim = ND_;   // 2048

    const float* A = (OP == 3) ? g_ao : Aparam;
    float* Cout = (OP == 0) ? g_q : (OP == 1) ? g_k : (OP == 2) ? g_v : Cparam;

    __shared__ float As[8][128];
    __shared__ float Bs[8][128];

    const int tid = threadIdx.x;
    const int m0 = blockIdx.y * 128;
    const int n0 = blockIdx.x * 128;
    const int tr = (tid >> 4) * 8;       // 0..120
    const int tc = (tid & 15) * 8;       // 0..120
    const int a_m = tid >> 1;            // 0..127
    const int a_k = (tid & 1) * 4;       // 0 or 4
    const int b_k = tid >> 5;            // 0..7
    const int b_n = (tid & 31) * 4;      // 0..124

    const float* Aptr = A + (size_t)(m0 + a_m) * Kdim + a_k;
    const float* Wptr = W + (size_t)b_k * Ndim + n0 + b_n;

    float acc[8][8];
#pragma unroll
    for (int i = 0; i < 8; i++)
#pragma unroll
        for (int j = 0; j < 8; j++) acc[i][j] = 0.0f;

    for (int k0 = 0; k0 < Kdim; k0 += 8) {
        float4 av = *(const float4*)(Aptr + k0);
        float4 bv = *(const float4*)(Wptr + (size_t)k0 * Ndim);
        __syncthreads();
        As[a_k + 0][a_m] = av.x;
        As[a_k + 1][a_m] = av.y;
        As[a_k + 2][a_m] = av.z;
        As[a_k + 3][a_m] = av.w;
        *(float4*)&Bs[b_k][b_n] = bv;
        __syncthreads();
#pragma unroll
        for (int kk = 0; kk < 8; kk++) {
            float a[8], bb[8];
            *(float4*)&a[0]  = *(const float4*)&As[kk][tr];
            *(float4*)&a[4]  = *(const float4*)&As[kk][tr + 4];
            *(float4*)&bb[0] = *(const float4*)&Bs[kk][tc];
            *(float4*)&bb[4] = *(const float4*)&Bs[kk][tc + 4];
#pragma unroll
            for (int i = 0; i < 8; i++)
#pragma unroll
                for (int j = 0; j < 8; j++) acc[i][j] += a[i] * bb[j];
        }
    }

    if (OP == 3) {
        // plain row-major [M, N]
#pragma unroll
        for (int i = 0; i < 8; i++) {
            float* dst = Cout + (size_t)(m0 + tr + i) * Ndim + n0 + tc;
            *(float4*)(dst + 0) = make_float4(acc[i][0], acc[i][1], acc[i][2], acc[i][3]);
            *(float4*)(dst + 4) = make_float4(acc[i][4], acc[i][5], acc[i][6], acc[i][7]);
        }
    } else {
        // store to (B,H,T,D); OP 0/1 with RoPE
#pragma unroll
        for (int i = 0; i < 8; i++) {
            int m = m0 + tr + i;
            int b = m >> 11;          // /T_
            int t = m & (T_ - 1);
#pragma unroll
            for (int j = 0; j < 8; j += 2) {
                int n = n0 + tc + j;
                int h = n >> 7;       // /D_
                int d = n & (D_ - 1); // even
                size_t di = (((size_t)(b * H_ + h) * T_ + t) * D_) + d;
                float xr = acc[i][j];
                float xi = acc[i][j + 1];
                if (OP <= 1) {
                    int d2 = d >> 1;
                    float cs = g_cos[t * (D_ / 2) + d2];
                    float sn = g_sin[t * (D_ / 2) + d2];
                    Cout[di]     = xr * cs - xi * sn;
                    Cout[di + 1] = xr * sn + xi * cs;
                } else {
                    Cout[di]     = xr;
                    Cout[di + 1] = xi;
                }
            }
        }
    }
}

// ---------------------------------------------------------------------------
// Flash attention, causal. BM=128 q rows per block, BN=64 k cols per iter.
// 512 threads = 16 warps; each warp owns 8 q-rows for softmax/PV; each lane
// owns 4 consecutive output dims (lane*4..lane*4+3).
// ---------------------------------------------------------------------------
#define ATTN_BM 128
#define ATTN_BN 64
#define QS_LD 129
#define KS_LD 129
// smem floats: Qs 128*129, Ks 64*129, Vs 64*128, Ss 128*64
#define ATTN_SMEM_FLOATS (ATTN_BM * QS_LD + ATTN_BN * KS_LD + ATTN_BN * D_ + ATTN_BM * ATTN_BN)
#define ATTN_SMEM_BYTES (ATTN_SMEM_FLOATS * 4)

__global__ void __launch_bounds__(512, 1) attn_kernel() {
    extern __shared__ float sm[];
    float* Qs = sm;                               // [128][129]
    float* Ks = Qs + ATTN_BM * QS_LD;             // [64][129]
    float* Vs = Ks + ATTN_BN * KS_LD;             // [64][128] (16B aligned)
    float* Ss = Vs + ATTN_BN * D_;                // [128][64]

    const int tid  = threadIdx.x;
    const int lane = tid & 31;
    const int wid  = tid >> 5;                    // 0..15
    const int bh   = blockIdx.y;                  // b*H + h
    const int b    = bh >> 4;
    const int h    = bh & (H_ - 1);
    const int q0   = blockIdx.x * ATTN_BM;

    const float* Qg = g_q + (size_t)bh * T_ * D_;
    const float* Kg = g_k + (size_t)bh * T_ * D_;
    const float* Vg = g_v + (size_t)bh * T_ * D_;

    // load Q tile (padded rows -> scalar stores)
    for (int i = tid; i < ATTN_BM * (D_ / 4); i += 512) {
        int r  = i >> 5;
        int c4 = (i & 31) * 4;
        float4 v = *(const float4*)(Qg + (size_t)(q0 + r) * D_ + c4);
        float* dst = Qs + r * QS_LD + c4;
        dst[0] = v.x; dst[1] = v.y; dst[2] = v.z; dst[3] = v.w;
    }

    float o[8][4];
    float mr[8], lr[8];
#pragma unroll
    for (int i = 0; i < 8; i++) {
        mr[i] = -1e30f;
        lr[i] = 0.0f;
#pragma unroll
        for (int c = 0; c < 4; c++) o[i][c] = 0.0f;
    }

    const int njt = 2 * blockIdx.x + 2;  // k tiles needed for causal coverage
    const float scale = 0.0883883476483184405f; // 1/sqrt(128)

    const int sr0 = (tid >> 4) * 4;  // S rows for this thread (0..124)
    const int sc0 = (tid & 15) * 4;  // S cols (0..60)

    for (int jt = 0; jt < njt; jt++) {
        const int k0 = jt * ATTN_BN;
        __syncthreads();  // prev PV done reading Vs/Ss
        // load K (padded) and V (unpadded)
        for (int i = tid; i < ATTN_BN * (D_ / 4); i += 512) {
            int r  = i >> 5;
            int c4 = (i & 31) * 4;
            float4 kv = *(const float4*)(Kg + (size_t)(k0 + r) * D_ + c4);
            float* kd = Ks + r * KS_LD + c4;
            kd[0] = kv.x; kd[1] = kv.y; kd[2] = kv.z; kd[3] = kv.w;
            float4 vv = *(const float4*)(Vg + (size_t)(k0 + r) * D_ + c4);
            *(float4*)(Vs + r * D_ + c4) = vv;
        }
        __syncthreads();

        // S = Q K^T (4x4 micro-tile per thread)
        float s[4][4];
#pragma unroll
        for (int i = 0; i < 4; i++)
#pragma unroll
            for (int j = 0; j < 4; j++) s[i][j] = 0.0f;

#pragma unroll 4
        for (int kk = 0; kk < D_; kk++) {
            float qv[4], kv[4];
#pragma unroll
            for (int i = 0; i < 4; i++) qv[i] = Qs[(sr0 + i) * QS_LD + kk];
#pragma unroll
            for (int j = 0; j < 4; j++) kv[j] = Ks[(sc0 + j) * KS_LD + kk];
#pragma unroll
            for (int i = 0; i < 4; i++)
#pragma unroll
                for (int j = 0; j < 4; j++) s[i][j] += qv[i] * kv[j];
        }
#pragma unroll
        for (int i = 0; i < 4; i++) {
            int qg = q0 + sr0 + i;
#pragma unroll
            for (int j = 0; j < 4; j++) {
                int kg = k0 + sc0 + j;
                Ss[(sr0 + i) * ATTN_BN + sc0 + j] =
                    (kg <= qg) ? s[i][j] * scale : -1e30f;
            }
        }
        __syncthreads();

        // online softmax + PV; warp `wid` owns rows wid*8 .. wid*8+7
#pragma unroll
        for (int r8 = 0; r8 < 8; r8++) {
            const int row = wid * 8 + r8;
            float s0 = Ss[row * ATTN_BN + lane];
            float s1 = Ss[row * ATTN_BN + lane + 32];
            float mx = fmaxf(s0, s1);
#pragma unroll
            for (int off = 16; off > 0; off >>= 1)
                mx = fmaxf(mx, __shfl_xor_sync(0xffffffffu, mx, off));
            float mnew = fmaxf(mr[r8], mx);
            float corr = __expf(mr[r8] - mnew);
            float p0 = __expf(s0 - mnew);
            float p1 = __expf(s1 - mnew);
            float ps = p0 + p1;
#pragma unroll
            for (int off = 16; off > 0; off >>= 1)
                ps += __shfl_xor_sync(0xffffffffu, ps, off);
            mr[r8] = mnew;
            lr[r8] = lr[r8] * corr + ps;
            Ss[row * ATTN_BN + lane]      = p0;
            Ss[row * ATTN_BN + lane + 32] = p1;
            __syncwarp();

            float oc0 = o[r8][0] * corr;
            float oc1 = o[r8][1] * corr;
            float oc2 = o[r8][2] * corr;
            float oc3 = o[r8][3] * corr;
#pragma unroll 8
            for (int j = 0; j < ATTN_BN; j++) {
                float p = Ss[row * ATTN_BN + j];
                float4 v = *(const float4*)(Vs + j * D_ + lane * 4);
                oc0 += p * v.x;
                oc1 += p * v.y;
                oc2 += p * v.z;
                oc3 += p * v.w;
            }
            o[r8][0] = oc0; o[r8][1] = oc1; o[r8][2] = oc2; o[r8][3] = oc3;
        }
    }

    // epilogue: normalize and store to (B,T,H*D)
#pragma unroll
    for (int r8 = 0; r8 < 8; r8++) {
        int row = wid * 8 + r8;
        int qg = q0 + row;
        float inv = 1.0f / lr[r8];
        float4 v = make_float4(o[r8][0] * inv, o[r8][1] * inv,
                               o[r8][2] * inv, o[r8][3] * inv);
        *(float4*)(g_ao + ((size_t)(b * T_ + qg) * C_) + h * D_ + lane * 4) = v;
    }
}

// ---------------------------------------------------------------------------
// Launch
// ---------------------------------------------------------------------------
extern "C" void kernel_launch(void* const* d_in, const int* in_sizes, int n_in,
                              void* d_out, int out_size) {
    const float* x  = (const float*)d_in[0];
    // d_in[1] = causal mask (tril) — known statically, unused
    const float* wq = (const float*)d_in[2];
    const float* wk = (const float*)d_in[3];
    const float* wv = (const float*)d_in[4];
    const float* wo = (const float*)d_in[5];
    float* out = (float*)d_out;

    rope_table_kernel<<<(T_ * (D_ / 2) + 255) / 256, 256>>>();

    dim3 gg(ND_ / 128, M_ / 128);  // (16, 32)
    gemm128_kernel<0><<<gg, 256>>>(x, wq, nullptr);
    gemm128_kernel<1><<<gg, 256>>>(x, wk, nullptr);
    gemm128_kernel<2><<<gg, 256>>>(x, wv, nullptr);

    cudaFuncSetAttribute(attn_kernel,
                         cudaFuncAttributeMaxDynamicSharedMemorySize,
                         ATTN_SMEM_BYTES);
    attn_kernel<<<dim3(T_ / ATTN_BM, B_ * H_), 512, ATTN_SMEM_BYTES>>>();

    gemm128_kernel<3><<<gg, 256>>>(nullptr, wo, out);
}

// round 3
// speedup vs baseline: 1.4689x; 1.4689x over previous
#include <cuda_runtime.h>
#include <cuda_bf16.h>
#include <math.h>
#include <stdint.h>

// Problem constants
#define B_ 2
#define T_ 2048
#define C_ 2048
#define H_ 16
#define D_ 128
#define M_ (B_ * T_)
#define ND_ (H_ * D_)

// ---------------------------------------------------------------------------
// Scratch
// ---------------------------------------------------------------------------
__device__ float g_q[(size_t)B_ * H_ * T_ * D_];   // (B,H,T,D)
__device__ float g_k[(size_t)B_ * H_ * T_ * D_];
__device__ float g_v[(size_t)B_ * H_ * T_ * D_];
__device__ float g_ao[(size_t)B_ * T_ * C_];       // attention out, (B,T,H*D)
__device__ float g_cos[T_ * (D_ / 2)];
__device__ float g_sin[T_ * (D_ / 2)];

// ---------------------------------------------------------------------------
// RoPE table
// ---------------------------------------------------------------------------
__global__ void rope_table_kernel() {
    int i = blockIdx.x * blockDim.x + threadIdx.x;
    if (i >= T_ * (D_ / 2)) return;
    int t  = i >> 6;
    int d2 = i & 63;
    float inv = powf(10000.0f, -((float)(2 * d2)) / (float)D_);
    float ang = (float)t * inv;
    g_cos[i] = cosf(ang);
    g_sin[i] = sinf(ang);
}

// ---------------------------------------------------------------------------
// mma.sync helpers (compute_103-safe: no tcgen05)
// ---------------------------------------------------------------------------
__device__ __forceinline__ uint32_t smem_u32(const void* p) {
    uint32_t a;
    asm("{ .reg .u64 t; cvta.to.shared.u64 t, %1; cvt.u32.u64 %0, t; }" : "=r"(a) : "l"(p));
    return a;
}
__device__ __forceinline__ void ldsm_x4(uint32_t* r, uint32_t addr) {
    asm volatile("ldmatrix.sync.aligned.m8n8.x4.shared.b16 {%0,%1,%2,%3}, [%4];"
                 : "=r"(r[0]), "=r"(r[1]), "=r"(r[2]), "=r"(r[3]) : "r"(addr));
}
__device__ __forceinline__ void ldsm_x4_t(uint32_t* r, uint32_t addr) {
    asm volatile("ldmatrix.sync.aligned.m8n8.x4.trans.shared.b16 {%0,%1,%2,%3}, [%4];"
                 : "=r"(r[0]), "=r"(r[1]), "=r"(r[2]), "=r"(r[3]) : "r"(addr));
}
__device__ __forceinline__ void mma_bf16(float* c, const uint32_t* a, const uint32_t* b) {
    asm volatile("mma.sync.aligned.m16n8k16.row.col.f32.bf16.bf16.f32 "
                 "{%0,%1,%2,%3}, {%4,%5,%6,%7}, {%8,%9}, {%0,%1,%2,%3};"
                 : "+f"(c[0]), "+f"(c[1]), "+f"(c[2]), "+f"(c[3])
                 : "r"(a[0]), "r"(a[1]), "r"(a[2]), "r"(a[3]), "r"(b[0]), "r"(b[1]));
}
__device__ __forceinline__ void cvt_hilo2(float x, float y, uint32_t& hi, uint32_t& lo) {
    __nv_bfloat16 hx = __float2bfloat16(x);
    __nv_bfloat16 hy = __float2bfloat16(y);
    __nv_bfloat16 lx = __float2bfloat16(x - __bfloat162float(hx));
    __nv_bfloat16 ly = __float2bfloat16(y - __bfloat162float(hy));
    hi = ((uint32_t)__bfloat16_as_ushort(hy) << 16) | __bfloat16_as_ushort(hx);
    lo = ((uint32_t)__bfloat16_as_ushort(ly) << 16) | __bfloat16_as_ushort(lx);
}

// ---------------------------------------------------------------------------
// bf16x3 GEMM via mma.sync: C[4096 x 2048] = A @ W (both fp32 in gmem).
// CTA tile 128x128, K-stage 32, register-prefetch double buffer.
// OP: 0 Q(+RoPE->g_q) 1 K(+RoPE->g_k) 2 V(->g_v) 3 out-proj (g_ao@wo -> C)
// ---------------------------------------------------------------------------
#define BK 32
#define A_LD 40        // halves per A row (pad for ldmatrix conflicts)
#define W_LD 136       // halves per W k-row (128 + 8 pad)
#define A_TILE_H (128 * A_LD)              // 5120 halves
#define W_TILE_H (BK * W_LD)               // 4352 halves
#define BUF_BYTES ((2 * A_TILE_H + 2 * W_TILE_H) * 2)   // 37888
#define GEMM_SMEM_BYTES (2 * BUF_BYTES)                  // 75776

template <int OP>
__global__ void __launch_bounds__(256, 1)
gemm_mma_kernel(const float* __restrict__ Aparam,
                const float* __restrict__ W,
                float* __restrict__ Cparam) {
    extern __shared__ char smem[];
    const uint32_t sb = smem_u32(smem);

    const float* A = (OP == 3) ? g_ao : Aparam;
    float* Cout = (OP == 0) ? g_q : (OP == 1) ? g_k : (OP == 2) ? g_v : Cparam;

    const int tid  = threadIdx.x;
    const int lane = tid & 31;
    const int wid  = tid >> 5;
    const int m0 = blockIdx.y * 128;
    const int n0 = blockIdx.x * 128;
    const int wm = (wid & 1) * 64;        // warp m-offset in tile
    const int wn = (wid >> 1) * 32;       // warp n-offset in tile

    float acc[4][4][4];
#pragma unroll
    for (int mt = 0; mt < 4; mt++)
#pragma unroll
        for (int nt = 0; nt < 4; nt++)
#pragma unroll
            for (int f = 0; f < 4; f++) acc[mt][nt][f] = 0.0f;

    // gmem staging mapping
    const int a_row = tid >> 3;           // 0..31 (+32*it)
    const int a_c4  = (tid & 7) * 4;      // k within stage
    const int w_krow = tid >> 5;          // 0..7 (+8*it)
    const int w_n4   = (tid & 31) * 4;

    // ldmatrix per-thread base offsets (halves)
    const int a_frag_off = (wm + (lane & 15)) * A_LD + (lane >> 4) * 8;
    const int b_frag_off = (lane & 15) * W_LD + wn + (lane >> 4) * 8;

    float4 ra[4], rw[4];

    // ---- prologue: stage 0 ----
    {
        const float* Ab = A + (size_t)(m0 + a_row) * 2048 + a_c4;
#pragma unroll
        for (int it = 0; it < 4; it++) ra[it] = *(const float4*)(Ab + (size_t)it * 32 * 2048);
        const float* Wb = W + (size_t)w_krow * 2048 + n0 + w_n4;
#pragma unroll
        for (int it = 0; it < 4; it++) rw[it] = *(const float4*)(Wb + (size_t)it * 8 * 2048);
    }

#define STORE_STAGE(BUFI) do {                                                   \
    char* ahi = smem + (BUFI) * BUF_BYTES;                                       \
    char* alo = ahi + A_TILE_H * 2;                                              \
    char* whi = alo + A_TILE_H * 2;                                              \
    char* wlo = whi + W_TILE_H * 2;                                              \
    _Pragma("unroll")                                                            \
    for (int it = 0; it < 4; it++) {                                             \
        int row = a_row + 32 * it;                                               \
        uint32_t h01, l01, h23, l23;                                             \
        cvt_hilo2(ra[it].x, ra[it].y, h01, l01);                                 \
        cvt_hilo2(ra[it].z, ra[it].w, h23, l23);                                 \
        int off = (row * A_LD + a_c4) * 2;                                       \
        *(uint2*)(ahi + off) = make_uint2(h01, h23);                             \
        *(uint2*)(alo + off) = make_uint2(l01, l23);                             \
    }                                                                            \
    _Pragma("unroll")                                                            \
    for (int it = 0; it < 4; it++) {                                             \
        int kr = w_krow + 8 * it;                                                \
        uint32_t h01, l01, h23, l23;                                             \
        cvt_hilo2(rw[it].x, rw[it].y, h01, l01);                                 \
        cvt_hilo2(rw[it].z, rw[it].w, h23, l23);                                 \
        int off = (kr * W_LD + w_n4) * 2;                                        \
        *(uint2*)(whi + off) = make_uint2(h01, h23);                             \
        *(uint2*)(wlo + off) = make_uint2(l01, l23);                             \
    }                                                                            \
} while (0)

    STORE_STAGE(0);
    __syncthreads();

    const int NS = 2048 / BK;   // 64
    for (int s = 0; s < NS; s++) {
        const int buf = s & 1;
        // prefetch next stage gmem -> regs
        if (s + 1 < NS) {
            const int k0 = (s + 1) * BK;
            const float* Ab = A + (size_t)(m0 + a_row) * 2048 + a_c4 + k0;
#pragma unroll
            for (int it = 0; it < 4; it++) ra[it] = *(const float4*)(Ab + (size_t)it * 32 * 2048);
            const float* Wb = W + (size_t)(k0 + w_krow) * 2048 + n0 + w_n4;
#pragma unroll
            for (int it = 0; it < 4; it++) rw[it] = *(const float4*)(Wb + (size_t)it * 8 * 2048);
        }

        // MMA over current buffer
        const uint32_t ahi = sb + buf * BUF_BYTES;
        const uint32_t alo = ahi + A_TILE_H * 2;
        const uint32_t whi = alo + A_TILE_H * 2;
        const uint32_t wlo = whi + W_TILE_H * 2;

#pragma unroll
        for (int ks = 0; ks < 2; ks++) {
            uint32_t ah[4][4], al[4][4];
#pragma unroll
            for (int mt = 0; mt < 4; mt++) {
                uint32_t ao = (a_frag_off + mt * 16 * A_LD + ks * 16) * 2;
                ldsm_x4(ah[mt], ahi + ao);
                ldsm_x4(al[mt], alo + ao);
            }
            uint32_t bh[2][4], bl[2][4];
#pragma unroll
            for (int np = 0; np < 2; np++) {
                uint32_t bo = (b_frag_off + ks * 16 * W_LD + np * 16) * 2;
                ldsm_x4_t(bh[np], whi + bo);
                ldsm_x4_t(bl[np], wlo + bo);
            }
#pragma unroll
            for (int mt = 0; mt < 4; mt++)
#pragma unroll
                for (int nt = 0; nt < 4; nt++) {
                    const uint32_t* bhp = &bh[nt >> 1][(nt & 1) * 2];
                    const uint32_t* blp = &bl[nt >> 1][(nt & 1) * 2];
                    mma_bf16(acc[mt][nt], ah[mt], bhp);
                    mma_bf16(acc[mt][nt], ah[mt], blp);
                    mma_bf16(acc[mt][nt], al[mt], bhp);
                }
        }

        if (s + 1 < NS) STORE_STAGE(buf ^ 1);
        __syncthreads();
    }
#undef STORE_STAGE

    // ---- epilogue: fused RoPE / layout ----
    const int lrow = lane >> 2;          // 0..7
    const int lcol = (lane & 3) * 2;     // even d within n8 tile
    const int h = blockIdx.x;            // BN == D_ so n-tile == head

#pragma unroll
    for (int mt = 0; mt < 4; mt++) {
#pragma unroll
        for (int rh = 0; rh < 2; rh++) {
            const int m = m0 + wm + mt * 16 + lrow + rh * 8;
            if (OP == 3) {
                float* dst = Cout + (size_t)m * ND_ + n0;
#pragma unroll
                for (int nt = 0; nt < 4; nt++) {
                    int d = wn + nt * 8 + lcol;
                    float x0 = acc[mt][nt][rh * 2 + 0];
                    float x1 = acc[mt][nt][rh * 2 + 1];
                    *(float2*)(dst + d) = make_float2(x0, x1);
                }
            } else {
                const int b = m >> 11;
                const int t = m & (T_ - 1);
                float* dst = Cout + (((size_t)(b * H_ + h) * T_ + t) << 7);
#pragma unroll
                for (int nt = 0; nt < 4; nt++) {
                    int d = wn + nt * 8 + lcol;
                    float x0 = acc[mt][nt][rh * 2 + 0];
                    float x1 = acc[mt][nt][rh * 2 + 1];
                    if (OP <= 1) {
                        float cs = g_cos[t * 64 + (d >> 1)];
                        float sn = g_sin[t * 64 + (d >> 1)];
                        *(float2*)(dst + d) = make_float2(x0 * cs - x1 * sn,
                                                          x0 * sn + x1 * cs);
                    } else {
                        *(float2*)(dst + d) = make_float2(x0, x1);
                    }
                }
            }
        }
    }
}

// ---------------------------------------------------------------------------
// Flash attention (fp32 SIMT, unchanged from round 1)
// ---------------------------------------------------------------------------
#define ATTN_BM 128
#define ATTN_BN 64
#define QS_LD 129
#define KS_LD 129
#define ATTN_SMEM_FLOATS (ATTN_BM * QS_LD + ATTN_BN * KS_LD + ATTN_BN * D_ + ATTN_BM * ATTN_BN)
#define ATTN_SMEM_BYTES (ATTN_SMEM_FLOATS * 4)

__global__ void __launch_bounds__(512, 1) attn_kernel() {
    extern __shared__ float sm[];
    float* Qs = sm;
    float* Ks = Qs + ATTN_BM * QS_LD;
    float* Vs = Ks + ATTN_BN * KS_LD;
    float* Ss = Vs + ATTN_BN * D_;

    const int tid  = threadIdx.x;
    const int lane = tid & 31;
    const int wid  = tid >> 5;
    const int bh   = blockIdx.y;
    const int b    = bh >> 4;
    const int h    = bh & (H_ - 1);
    const int q0   = blockIdx.x * ATTN_BM;

    const float* Qg = g_q + (size_t)bh * T_ * D_;
    const float* Kg = g_k + (size_t)bh * T_ * D_;
    const float* Vg = g_v + (size_t)bh * T_ * D_;

    for (int i = tid; i < ATTN_BM * (D_ / 4); i += 512) {
        int r  = i >> 5;
        int c4 = (i & 31) * 4;
        float4 v = *(const float4*)(Qg + (size_t)(q0 + r) * D_ + c4);
        float* dst = Qs + r * QS_LD + c4;
        dst[0] = v.x; dst[1] = v.y; dst[2] = v.z; dst[3] = v.w;
    }

    float o[8][4];
    float mr[8], lr[8];
#pragma unroll
    for (int i = 0; i < 8; i++) {
        mr[i] = -1e30f; lr[i] = 0.0f;
#pragma unroll
        for (int c = 0; c < 4; c++) o[i][c] = 0.0f;
    }

    const int njt = 2 * blockIdx.x + 2;
    const float scale = 0.0883883476483184405f;
    const int sr0 = (tid >> 4) * 4;
    const int sc0 = (tid & 15) * 4;

    for (int jt = 0; jt < njt; jt++) {
        const int k0 = jt * ATTN_BN;
        __syncthreads();
        for (int i = tid; i < ATTN_BN * (D_ / 4); i += 512) {
            int r  = i >> 5;
            int c4 = (i & 31) * 4;
            float4 kv = *(const float4*)(Kg + (size_t)(k0 + r) * D_ + c4);
            float* kd = Ks + r * KS_LD + c4;
            kd[0] = kv.x; kd[1] = kv.y; kd[2] = kv.z; kd[3] = kv.w;
            float4 vv = *(const float4*)(Vg + (size_t)(k0 + r) * D_ + c4);
            *(float4*)(Vs + r * D_ + c4) = vv;
        }
        __syncthreads();

        float s[4][4];
#pragma unroll
        for (int i = 0; i < 4; i++)
#pragma unroll
            for (int j = 0; j < 4; j++) s[i][j] = 0.0f;

#pragma unroll 4
        for (int kk = 0; kk < D_; kk++) {
            float qv[4], kv[4];
#pragma unroll
            for (int i = 0; i < 4; i++) qv[i] = Qs[(sr0 + i) * QS_LD + kk];
#pragma unroll
            for (int j = 0; j < 4; j++) kv[j] = Ks[(sc0 + j) * KS_LD + kk];
#pragma unroll
            for (int i = 0; i < 4; i++)
#pragma unroll
                for (int j = 0; j < 4; j++) s[i][j] += qv[i] * kv[j];
        }
#pragma unroll
        for (int i = 0; i < 4; i++) {
            int qg = q0 + sr0 + i;
#pragma unroll
            for (int j = 0; j < 4; j++) {
                int kg = k0 + sc0 + j;
                Ss[(sr0 + i) * ATTN_BN + sc0 + j] =
                    (kg <= qg) ? s[i][j] * scale : -1e30f;
            }
        }
        __syncthreads();

#pragma unroll
        for (int r8 = 0; r8 < 8; r8++) {
            const int row = wid * 8 + r8;
            float s0 = Ss[row * ATTN_BN + lane];
            float s1 = Ss[row * ATTN_BN + lane + 32];
            float mx = fmaxf(s0, s1);
#pragma unroll
            for (int off = 16; off > 0; off >>= 1)
                mx = fmaxf(mx, __shfl_xor_sync(0xffffffffu, mx, off));
            float mnew = fmaxf(mr[r8], mx);
            float corr = __expf(mr[r8] - mnew);
            float p0 = __expf(s0 - mnew);
            float p1 = __expf(s1 - mnew);
            float ps = p0 + p1;
#pragma unroll
            for (int off = 16; off > 0; off >>= 1)
                ps += __shfl_xor_sync(0xffffffffu, ps, off);
            mr[r8] = mnew;
            lr[r8] = lr[r8] * corr + ps;
            Ss[row * ATTN_BN + lane]      = p0;
            Ss[row * ATTN_BN + lane + 32] = p1;
            __syncwarp();

            float oc0 = o[r8][0] * corr;
            float oc1 = o[r8][1] * corr;
            float oc2 = o[r8][2] * corr;
            float oc3 = o[r8][3] * corr;
#pragma unroll 8
            for (int j = 0; j < ATTN_BN; j++) {
                float p = Ss[row * ATTN_BN + j];
                float4 v = *(const float4*)(Vs + j * D_ + lane * 4);
                oc0 += p * v.x;
                oc1 += p * v.y;
                oc2 += p * v.z;
                oc3 += p * v.w;
            }
            o[r8][0] = oc0; o[r8][1] = oc1; o[r8][2] = oc2; o[r8][3] = oc3;
        }
    }

#pragma unroll
    for (int r8 = 0; r8 < 8; r8++) {
        int row = wid * 8 + r8;
        int qg = q0 + row;
        float inv = 1.0f / lr[r8];
        float4 v = make_float4(o[r8][0] * inv, o[r8][1] * inv,
                               o[r8][2] * inv, o[r8][3] * inv);
        *(float4*)(g_ao + ((size_t)(b * T_ + qg) * C_) + h * D_ + lane * 4) = v;
    }
}

// ---------------------------------------------------------------------------
// Launch
// ---------------------------------------------------------------------------
extern "C" void kernel_launch(void* const* d_in, const int* in_sizes, int n_in,
                              void* d_out, int out_size) {
    const float* x  = (const float*)d_in[0];
    const float* wq = (const float*)d_in[2];
    const float* wk = (const float*)d_in[3];
    const float* wv = (const float*)d_in[4];
    const float* wo = (const float*)d_in[5];
    float* out = (float*)d_out;

    rope_table_kernel<<<(T_ * (D_ / 2) + 255) / 256, 256>>>();

    cudaFuncSetAttribute(gemm_mma_kernel<0>, cudaFuncAttributeMaxDynamicSharedMemorySize, GEMM_SMEM_BYTES);
    cudaFuncSetAttribute(gemm_mma_kernel<1>, cudaFuncAttributeMaxDynamicSharedMemorySize, GEMM_SMEM_BYTES);
    cudaFuncSetAttribute(gemm_mma_kernel<2>, cudaFuncAttributeMaxDynamicSharedMemorySize, GEMM_SMEM_BYTES);
    cudaFuncSetAttribute(gemm_mma_kernel<3>, cudaFuncAttributeMaxDynamicSharedMemorySize, GEMM_SMEM_BYTES);

    dim3 gg(ND_ / 128, M_ / 128);  // (16, 32)
    gemm_mma_kernel<0><<<gg, 256, GEMM_SMEM_BYTES>>>(x, wq, nullptr);
    gemm_mma_kernel<1><<<gg, 256, GEMM_SMEM_BYTES>>>(x, wk, nullptr);
    gemm_mma_kernel<2><<<gg, 256, GEMM_SMEM_BYTES>>>(x, wv, nullptr);

    cudaFuncSetAttribute(attn_kernel, cudaFuncAttributeMaxDynamicSharedMemorySize, ATTN_SMEM_BYTES);
    attn_kernel<<<dim3(T_ / ATTN_BM, B_ * H_), 512, ATTN_SMEM_BYTES>>>();

    gemm_mma_kernel<3><<<gg, 256, GEMM_SMEM_BYTES>>>(nullptr, wo, out);
}

// round 5
// speedup vs baseline: 2.7323x; 1.8600x over previous
#include <cuda_runtime.h>
#include <cuda_bf16.h>
#include <math.h>
#include <stdint.h>

// Problem constants
#define B_ 2
#define T_ 2048
#define C_ 2048
#define H_ 16
#define D_ 128
#define M_ (B_ * T_)
#define ND_ (H_ * D_)

// ---------------------------------------------------------------------------
// Scratch
// ---------------------------------------------------------------------------
__device__ float g_q[(size_t)B_ * H_ * T_ * D_];   // (B,H,T,D)
__device__ float g_k[(size_t)B_ * H_ * T_ * D_];
__device__ float g_v[(size_t)B_ * H_ * T_ * D_];
__device__ float g_ao[(size_t)B_ * T_ * C_];       // attention out, (B,T,H*D)
__device__ float g_cos[T_ * (D_ / 2)];
__device__ float g_sin[T_ * (D_ / 2)];

// ---------------------------------------------------------------------------
// RoPE table
// ---------------------------------------------------------------------------
__global__ void rope_table_kernel() {
    int i = blockIdx.x * blockDim.x + threadIdx.x;
    if (i >= T_ * (D_ / 2)) return;
    int t  = i >> 6;
    int d2 = i & 63;
    float inv = powf(10000.0f, -((float)(2 * d2)) / (float)D_);
    float ang = (float)t * inv;
    g_cos[i] = cosf(ang);
    g_sin[i] = sinf(ang);
}

// ---------------------------------------------------------------------------
// mma.sync helpers (compute_103-safe: no tcgen05)
// ---------------------------------------------------------------------------
__device__ __forceinline__ uint32_t smem_u32(const void* p) {
    uint32_t a;
    asm("{ .reg .u64 t; cvta.to.shared.u64 t, %1; cvt.u32.u64 %0, t; }" : "=r"(a) : "l"(p));
    return a;
}
__device__ __forceinline__ void ldsm_x4(uint32_t* r, uint32_t addr) {
    asm volatile("ldmatrix.sync.aligned.m8n8.x4.shared.b16 {%0,%1,%2,%3}, [%4];"
                 : "=r"(r[0]), "=r"(r[1]), "=r"(r[2]), "=r"(r[3]) : "r"(addr));
}
__device__ __forceinline__ void ldsm_x4_t(uint32_t* r, uint32_t addr) {
    asm volatile("ldmatrix.sync.aligned.m8n8.x4.trans.shared.b16 {%0,%1,%2,%3}, [%4];"
                 : "=r"(r[0]), "=r"(r[1]), "=r"(r[2]), "=r"(r[3]) : "r"(addr));
}
__device__ __forceinline__ void mma_bf16(float* c, const uint32_t* a, const uint32_t* b) {
    asm volatile("mma.sync.aligned.m16n8k16.row.col.f32.bf16.bf16.f32 "
                 "{%0,%1,%2,%3}, {%4,%5,%6,%7}, {%8,%9}, {%0,%1,%2,%3};"
                 : "+f"(c[0]), "+f"(c[1]), "+f"(c[2]), "+f"(c[3])
                 : "r"(a[0]), "r"(a[1]), "r"(a[2]), "r"(a[3]), "r"(b[0]), "r"(b[1]));
}
__device__ __forceinline__ void cvt_hilo2(float x, float y, uint32_t& hi, uint32_t& lo) {
    __nv_bfloat16 hx = __float2bfloat16(x);
    __nv_bfloat16 hy = __float2bfloat16(y);
    __nv_bfloat16 lx = __float2bfloat16(x - __bfloat162float(hx));
    __nv_bfloat16 ly = __float2bfloat16(y - __bfloat162float(hy));
    hi = ((uint32_t)__bfloat16_as_ushort(hy) << 16) | __bfloat16_as_ushort(hx);
    lo = ((uint32_t)__bfloat16_as_ushort(ly) << 16) | __bfloat16_as_ushort(lx);
}
// exp2 on the FMA pipe (avoids MUFU bottleneck); |err| ~1e-7 on [-0.5, 0.5]
__device__ __forceinline__ float exp2p(float t) {
    t = fmaxf(t, -100.0f);
    float nf = rintf(t);
    float f = t - nf;
    float p =             1.3333558146e-3f;
    p = fmaf(p, f, 9.6181291076e-3f);
    p = fmaf(p, f, 5.5504108665e-2f);
    p = fmaf(p, f, 2.4022650696e-1f);
    p = fmaf(p, f, 6.9314718056e-1f);
    p = fmaf(p, f, 1.0f);
    float sc = __int_as_float(((int)nf + 127) << 23);
    return p * sc;
}

// ---------------------------------------------------------------------------
// bf16x3 GEMM via mma.sync (unchanged from round 3)
// ---------------------------------------------------------------------------
#define BK 32
#define A_LD 40
#define W_LD 136
#define A_TILE_H (128 * A_LD)
#define W_TILE_H (BK * W_LD)
#define BUF_BYTES ((2 * A_TILE_H + 2 * W_TILE_H) * 2)
#define GEMM_SMEM_BYTES (2 * BUF_BYTES)

template <int OP>
__global__ void __launch_bounds__(256, 1)
gemm_mma_kernel(const float* __restrict__ Aparam,
                const float* __restrict__ W,
                float* __restrict__ Cparam) {
    extern __shared__ char smem[];
    const uint32_t sb = smem_u32(smem);

    const float* A = (OP == 3) ? g_ao : Aparam;
    float* Cout = (OP == 0) ? g_q : (OP == 1) ? g_k : (OP == 2) ? g_v : Cparam;

    const int tid  = threadIdx.x;
    const int lane = tid & 31;
    const int wid  = tid >> 5;
    const int m0 = blockIdx.y * 128;
    const int n0 = blockIdx.x * 128;
    const int wm = (wid & 1) * 64;
    const int wn = (wid >> 1) * 32;

    float acc[4][4][4];
#pragma unroll
    for (int mt = 0; mt < 4; mt++)
#pragma unroll
        for (int nt = 0; nt < 4; nt++)
#pragma unroll
            for (int f = 0; f < 4; f++) acc[mt][nt][f] = 0.0f;

    const int a_row = tid >> 3;
    const int a_c4  = (tid & 7) * 4;
    const int w_krow = tid >> 5;
    const int w_n4   = (tid & 31) * 4;

    const int a_frag_off = (wm + (lane & 15)) * A_LD + (lane >> 4) * 8;
    const int b_frag_off = (lane & 15) * W_LD + wn + (lane >> 4) * 8;

    float4 ra[4], rw[4];
    {
        const float* Ab = A + (size_t)(m0 + a_row) * 2048 + a_c4;
#pragma unroll
        for (int it = 0; it < 4; it++) ra[it] = *(const float4*)(Ab + (size_t)it * 32 * 2048);
        const float* Wb = W + (size_t)w_krow * 2048 + n0 + w_n4;
#pragma unroll
        for (int it = 0; it < 4; it++) rw[it] = *(const float4*)(Wb + (size_t)it * 8 * 2048);
    }

#define STORE_STAGE(BUFI) do {                                                   \
    char* ahi = smem + (BUFI) * BUF_BYTES;                                       \
    char* alo = ahi + A_TILE_H * 2;                                              \
    char* whi = alo + A_TILE_H * 2;                                              \
    char* wlo = whi + W_TILE_H * 2;                                              \
    _Pragma("unroll")                                                            \
    for (int it = 0; it < 4; it++) {                                             \
        int row = a_row + 32 * it;                                               \
        uint32_t h01, l01, h23, l23;                                             \
        cvt_hilo2(ra[it].x, ra[it].y, h01, l01);                                 \
        cvt_hilo2(ra[it].z, ra[it].w, h23, l23);                                 \
        int off = (row * A_LD + a_c4) * 2;                                       \
        *(uint2*)(ahi + off) = make_uint2(h01, h23);                             \
        *(uint2*)(alo + off) = make_uint2(l01, l23);                             \
    }                                                                            \
    _Pragma("unroll")                                                            \
    for (int it = 0; it < 4; it++) {                                             \
        int kr = w_krow + 8 * it;                                                \
        uint32_t h01, l01, h23, l23;                                             \
        cvt_hilo2(rw[it].x, rw[it].y, h01, l01);                                 \
        cvt_hilo2(rw[it].z, rw[it].w, h23, l23);                                 \
        int off = (kr * W_LD + w_n4) * 2;                                        \
        *(uint2*)(whi + off) = make_uint2(h01, h23);                             \
        *(uint2*)(wlo + off) = make_uint2(l01, l23);                             \
    }                                                                            \
} while (0)

    STORE_STAGE(0);
    __syncthreads();

    const int NS = 2048 / BK;
    for (int s = 0; s < NS; s++) {
        const int buf = s & 1;
        if (s + 1 < NS) {
            const int k0 = (s + 1) * BK;
            const float* Ab = A + (size_t)(m0 + a_row) * 2048 + a_c4 + k0;
#pragma unroll
            for (int it = 0; it < 4; it++) ra[it] = *(const float4*)(Ab + (size_t)it * 32 * 2048);
            const float* Wb = W + (size_t)(k0 + w_krow) * 2048 + n0 + w_n4;
#pragma unroll
            for (int it = 0; it < 4; it++) rw[it] = *(const float4*)(Wb + (size_t)it * 8 * 2048);
        }

        const uint32_t ahi = sb + buf * BUF_BYTES;
        const uint32_t alo = ahi + A_TILE_H * 2;
        const uint32_t whi = alo + A_TILE_H * 2;
        const uint32_t wlo = whi + W_TILE_H * 2;

#pragma unroll
        for (int ks = 0; ks < 2; ks++) {
            uint32_t ah[4][4], al[4][4];
#pragma unroll
            for (int mt = 0; mt < 4; mt++) {
                uint32_t ao = (a_frag_off + mt * 16 * A_LD + ks * 16) * 2;
                ldsm_x4(ah[mt], ahi + ao);
                ldsm_x4(al[mt], alo + ao);
            }
            uint32_t bh[2][4], bl[2][4];
#pragma unroll
            for (int np = 0; np < 2; np++) {
                uint32_t bo = (b_frag_off + ks * 16 * W_LD + np * 16) * 2;
                ldsm_x4_t(bh[np], whi + bo);
                ldsm_x4_t(bl[np], wlo + bo);
            }
#pragma unroll
            for (int mt = 0; mt < 4; mt++)
#pragma unroll
                for (int nt = 0; nt < 4; nt++) {
                    const uint32_t* bhp = &bh[nt >> 1][(nt & 1) * 2];
                    const uint32_t* blp = &bl[nt >> 1][(nt & 1) * 2];
                    mma_bf16(acc[mt][nt], ah[mt], bhp);
                    mma_bf16(acc[mt][nt], ah[mt], blp);
                    mma_bf16(acc[mt][nt], al[mt], bhp);
                }
        }

        if (s + 1 < NS) STORE_STAGE(buf ^ 1);
        __syncthreads();
    }
#undef STORE_STAGE

    const int lrow = lane >> 2;
    const int lcol = (lane & 3) * 2;
    const int h = blockIdx.x;

#pragma unroll
    for (int mt = 0; mt < 4; mt++) {
#pragma unroll
        for (int rh = 0; rh < 2; rh++) {
            const int m = m0 + wm + mt * 16 + lrow + rh * 8;
            if (OP == 3) {
                float* dst = Cout + (size_t)m * ND_ + n0;
#pragma unroll
                for (int nt = 0; nt < 4; nt++) {
                    int d = wn + nt * 8 + lcol;
                    float x0 = acc[mt][nt][rh * 2 + 0];
                    float x1 = acc[mt][nt][rh * 2 + 1];
                    *(float2*)(dst + d) = make_float2(x0, x1);
                }
            } else {
                const int b = m >> 11;
                const int t = m & (T_ - 1);
                float* dst = Cout + (((size_t)(b * H_ + h) * T_ + t) << 7);
#pragma unroll
                for (int nt = 0; nt < 4; nt++) {
                    int d = wn + nt * 8 + lcol;
                    float x0 = acc[mt][nt][rh * 2 + 0];
                    float x1 = acc[mt][nt][rh * 2 + 1];
                    if (OP <= 1) {
                        float cs = g_cos[t * 64 + (d >> 1)];
                        float sn = g_sin[t * 64 + (d >> 1)];
                        *(float2*)(dst + d) = make_float2(x0 * cs - x1 * sn,
                                                          x0 * sn + x1 * cs);
                    } else {
                        *(float2*)(dst + d) = make_float2(x0, x1);
                    }
                }
            }
        }
    }
}

// ---------------------------------------------------------------------------
// Tensor-core flash attention.
// BM=128 q rows / CTA, 8 warps (16 rows each), K-tile BN=64, D=128.
// QK^T in bf16x3; softmax via FFMA exp2; PV ALSO in bf16x3
// (Phi*Vhi + Phi*Vlo + Plo*Vhi) to stay under the 1e-3 error budget.
// Q scaled by log2(e)/sqrt(D) at load so scores are in base-2 units.
// ---------------------------------------------------------------------------
#define Q_LD 136
#define K_LD 136
#define V_LD 136
#define QHI_OFF 0
#define QLO_OFF (QHI_OFF + 128 * Q_LD * 2)     // 34816
#define KHI_OFF (QLO_OFF + 128 * Q_LD * 2)     // 69632
#define KLO_OFF (KHI_OFF + 64 * K_LD * 2)      // 87040
#define VHI_OFF (KLO_OFF + 64 * K_LD * 2)      // 104448
#define VLO_OFF (VHI_OFF + 64 * V_LD * 2)      // 121856
#define ATT_SMEM (VLO_OFF + 64 * V_LD * 2)     // 139264

__global__ void __launch_bounds__(256, 1) attn_mma_kernel() {
    extern __shared__ char smc[];
    const uint32_t sb = smem_u32(smc);
    const int tid  = threadIdx.x;
    const int lane = tid & 31;
    const int wid  = tid >> 5;
    const int bh   = blockIdx.y;
    const int b    = bh >> 4;
    const int h    = bh & (H_ - 1);
    const int q0   = blockIdx.x * 128;
    const int wm   = wid * 16;
    const int lrow = lane >> 2;
    const int lcol2 = (lane & 3) * 2;

    const float* Qg = g_q + (size_t)bh * T_ * D_;
    const float* Kg = g_k + (size_t)bh * T_ * D_;
    const float* Vg = g_v + (size_t)bh * T_ * D_;

    // ---- load Q once: scale by log2(e)/sqrt(128), split hi/lo ----
    const float qs = 0.0883883476483184405f * 1.4426950408889634f;
    for (int it = 0; it < 16; it++) {
        int i  = it * 256 + tid;
        int r  = i >> 5;
        int c4 = (i & 31) * 4;
        float4 v = *(const float4*)(Qg + (size_t)(q0 + r) * D_ + c4);
        uint32_t h01, l01, h23, l23;
        cvt_hilo2(v.x * qs, v.y * qs, h01, l01);
        cvt_hilo2(v.z * qs, v.w * qs, h23, l23);
        int off = (r * Q_LD + c4) * 2;
        *(uint2*)(smc + QHI_OFF + off) = make_uint2(h01, h23);
        *(uint2*)(smc + QLO_OFF + off) = make_uint2(l01, l23);
    }

    // frag base addresses
    const uint32_t aq_base = sb + QHI_OFF + ((wm + (lane & 15)) * Q_LD + (lane >> 4) * 8) * 2;
    const uint32_t aq_lo_d = QLO_OFF - QHI_OFF;
    const int kb_row = (lane & 7) + ((lane >> 4) << 3);
    const int kb_col = ((lane >> 3) & 1) << 3;
    const uint32_t kb_base = sb + KHI_OFF + (kb_row * K_LD + kb_col) * 2;
    const uint32_t kb_lo_d = KLO_OFF - KHI_OFF;
    const uint32_t vh_base = sb + VHI_OFF + ((lane & 15) * V_LD + (lane >> 4) * 8) * 2;
    const uint32_t vb_lo_d = VLO_OFF - VHI_OFF;

    float o[16][4];
#pragma unroll
    for (int dt = 0; dt < 16; dt++)
#pragma unroll
        for (int f = 0; f < 4; f++) o[dt][f] = 0.0f;
    float m0 = -1e30f, m1 = -1e30f, l0 = 0.0f, l1 = 0.0f;

    const int njt = 2 * blockIdx.x + 2;

    for (int jt = 0; jt < njt; jt++) {
        const int k0 = jt * 64;
        __syncthreads();  // previous iteration done reading K/V (also Q store barrier)
        // ---- load K (hi/lo) and V (hi/lo) tiles ----
        for (int it = 0; it < 8; it++) {
            int i  = it * 256 + tid;
            int r  = i >> 5;
            int c4 = (i & 31) * 4;
            float4 kv = *(const float4*)(Kg + (size_t)(k0 + r) * D_ + c4);
            uint32_t h01, l01, h23, l23;
            cvt_hilo2(kv.x, kv.y, h01, l01);
            cvt_hilo2(kv.z, kv.w, h23, l23);
            int off = (r * K_LD + c4) * 2;
            *(uint2*)(smc + KHI_OFF + off) = make_uint2(h01, h23);
            *(uint2*)(smc + KLO_OFF + off) = make_uint2(l01, l23);
            float4 vv = *(const float4*)(Vg + (size_t)(k0 + r) * D_ + c4);
            uint32_t vh01, vl01, vh23, vl23;
            cvt_hilo2(vv.x, vv.y, vh01, vl01);
            cvt_hilo2(vv.z, vv.w, vh23, vl23);
            int voff = (r * V_LD + c4) * 2;
            *(uint2*)(smc + VHI_OFF + voff) = make_uint2(vh01, vh23);
            *(uint2*)(smc + VLO_OFF + voff) = make_uint2(vl01, vl23);
        }
        __syncthreads();

        // ---- S = Q K^T (bf16x3), 8 n-tiles of 8 cols ----
        float s[8][4];
#pragma unroll
        for (int nt = 0; nt < 8; nt++)
#pragma unroll
            for (int f = 0; f < 4; f++) s[nt][f] = 0.0f;

#pragma unroll
        for (int ks = 0; ks < 8; ks++) {
            uint32_t ah[4], al[4];
            ldsm_x4(ah, aq_base + ks * 32);
            ldsm_x4(al, aq_base + aq_lo_d + ks * 32);
#pragma unroll
            for (int np = 0; np < 4; np++) {
                uint32_t kh[4], kl[4];
                uint32_t off = (uint32_t)(np * (16 * K_LD * 2) + ks * 32);
                ldsm_x4(kh, kb_base + off);
                ldsm_x4(kl, kb_base + kb_lo_d + off);
                mma_bf16(s[2 * np],     ah, kh);
                mma_bf16(s[2 * np],     ah, kl);
                mma_bf16(s[2 * np],     al, kh);
                mma_bf16(s[2 * np + 1], ah, kh + 2);
                mma_bf16(s[2 * np + 1], ah, kl + 2);
                mma_bf16(s[2 * np + 1], al, kh + 2);
            }
        }

        // ---- causal mask (diagonal tiles only) ----
        if (k0 + 63 > q0 + wm) {
            const int row0 = q0 + wm + lrow;
            const int row1 = row0 + 8;
#pragma unroll
            for (int nt = 0; nt < 8; nt++) {
                int c0 = k0 + nt * 8 + lcol2;
                if (c0 > row0)     s[nt][0] = -1e30f;
                if (c0 + 1 > row0) s[nt][1] = -1e30f;
                if (c0 > row1)     s[nt][2] = -1e30f;
                if (c0 + 1 > row1) s[nt][3] = -1e30f;
            }
        }

        // ---- online softmax (base 2) ----
        float mx0 = -1e30f, mx1 = -1e30f;
#pragma unroll
        for (int nt = 0; nt < 8; nt++) {
            mx0 = fmaxf(mx0, fmaxf(s[nt][0], s[nt][1]));
            mx1 = fmaxf(mx1, fmaxf(s[nt][2], s[nt][3]));
        }
        mx0 = fmaxf(mx0, __shfl_xor_sync(0xffffffffu, mx0, 1));
        mx0 = fmaxf(mx0, __shfl_xor_sync(0xffffffffu, mx0, 2));
        mx1 = fmaxf(mx1, __shfl_xor_sync(0xffffffffu, mx1, 1));
        mx1 = fmaxf(mx1, __shfl_xor_sync(0xffffffffu, mx1, 2));
        float m0n = fmaxf(m0, mx0);
        float m1n = fmaxf(m1, mx1);
        float corr0 = exp2p(m0 - m0n);
        float corr1 = exp2p(m1 - m1n);
        m0 = m0n; m1 = m1n;

        uint32_t ph01[8], ph23[8], pl01[8], pl23[8];
        float sum0 = 0.0f, sum1 = 0.0f;
#pragma unroll
        for (int nt = 0; nt < 8; nt++) {
            float p0 = exp2p(s[nt][0] - m0);
            float p1 = exp2p(s[nt][1] - m0);
            float p2 = exp2p(s[nt][2] - m1);
            float p3 = exp2p(s[nt][3] - m1);
            sum0 += p0 + p1;
            sum1 += p2 + p3;
            cvt_hilo2(p0, p1, ph01[nt], pl01[nt]);
            cvt_hilo2(p2, p3, ph23[nt], pl23[nt]);
        }
        sum0 += __shfl_xor_sync(0xffffffffu, sum0, 1);
        sum0 += __shfl_xor_sync(0xffffffffu, sum0, 2);
        sum1 += __shfl_xor_sync(0xffffffffu, sum1, 1);
        sum1 += __shfl_xor_sync(0xffffffffu, sum1, 2);
        l0 = l0 * corr0 + sum0;
        l1 = l1 * corr1 + sum1;

#pragma unroll
        for (int dt = 0; dt < 16; dt++) {
            o[dt][0] *= corr0; o[dt][1] *= corr0;
            o[dt][2] *= corr1; o[dt][3] *= corr1;
        }

        // ---- O += P V (bf16x3: Phi*Vhi + Phi*Vlo + Plo*Vhi) ----
#pragma unroll
        for (int ks = 0; ks < 4; ks++) {
            uint32_t aph[4] = { ph01[2 * ks], ph23[2 * ks], ph01[2 * ks + 1], ph23[2 * ks + 1] };
            uint32_t apl[4] = { pl01[2 * ks], pl23[2 * ks], pl01[2 * ks + 1], pl23[2 * ks + 1] };
#pragma unroll
            for (int np = 0; np < 8; np++) {
                uint32_t vh[4], vl[4];
                uint32_t off = (uint32_t)(ks * (16 * V_LD * 2) + np * 32);
                ldsm_x4_t(vh, vh_base + off);
                ldsm_x4_t(vl, vh_base + vb_lo_d + off);
                mma_bf16(o[2 * np],     aph, vh);
                mma_bf16(o[2 * np],     aph, vl);
                mma_bf16(o[2 * np],     apl, vh);
                mma_bf16(o[2 * np + 1], aph, vh + 2);
                mma_bf16(o[2 * np + 1], aph, vl + 2);
                mma_bf16(o[2 * np + 1], apl, vh + 2);
            }
        }
    }

    // ---- epilogue: normalize, store to (B,T,H*D) ----
    const float inv0 = 1.0f / l0;
    const float inv1 = 1.0f / l1;
    const int row0 = q0 + wm + lrow;
    const int row1 = row0 + 8;
    float* dst0 = g_ao + (size_t)(b * T_ + row0) * C_ + h * D_;
    float* dst1 = g_ao + (size_t)(b * T_ + row1) * C_ + h * D_;
#pragma unroll
    for (int dt = 0; dt < 16; dt++) {
        int d = dt * 8 + lcol2;
        *(float2*)(dst0 + d) = make_float2(o[dt][0] * inv0, o[dt][1] * inv0);
        *(float2*)(dst1 + d) = make_float2(o[dt][2] * inv1, o[dt][3] * inv1);
    }
}

// ---------------------------------------------------------------------------
// Launch
// ---------------------------------------------------------------------------
extern "C" void kernel_launch(void* const* d_in, const int* in_sizes, int n_in,
                              void* d_out, int out_size) {
    const float* x  = (const float*)d_in[0];
    const float* wq = (const float*)d_in[2];
    const float* wk = (const float*)d_in[3];
    const float* wv = (const float*)d_in[4];
    const float* wo = (const float*)d_in[5];
    float* out = (float*)d_out;

    rope_table_kernel<<<(T_ * (D_ / 2) + 255) / 256, 256>>>();

    cudaFuncSetAttribute(gemm_mma_kernel<0>, cudaFuncAttributeMaxDynamicSharedMemorySize, GEMM_SMEM_BYTES);
    cudaFuncSetAttribute(gemm_mma_kernel<1>, cudaFuncAttributeMaxDynamicSharedMemorySize, GEMM_SMEM_BYTES);
    cudaFuncSetAttribute(gemm_mma_kernel<2>, cudaFuncAttributeMaxDynamicSharedMemorySize, GEMM_SMEM_BYTES);
    cudaFuncSetAttribute(gemm_mma_kernel<3>, cudaFuncAttributeMaxDynamicSharedMemorySize, GEMM_SMEM_BYTES);
    cudaFuncSetAttribute(attn_mma_kernel,    cudaFuncAttributeMaxDynamicSharedMemorySize, ATT_SMEM);

    dim3 gg(ND_ / 128, M_ / 128);  // (16, 32)
    gemm_mma_kernel<0><<<gg, 256, GEMM_SMEM_BYTES>>>(x, wq, nullptr);
    gemm_mma_kernel<1><<<gg, 256, GEMM_SMEM_BYTES>>>(x, wk, nullptr);
    gemm_mma_kernel<2><<<gg, 256, GEMM_SMEM_BYTES>>>(x, wv, nullptr);

    attn_mma_kernel<<<dim3(T_ / 128, B_ * H_), 256, ATT_SMEM>>>();

    gemm_mma_kernel<3><<<gg, 256, GEMM_SMEM_BYTES>>>(nullptr, wo, out);
}

// round 6
// speedup vs baseline: 2.7337x; 1.0005x over previous
#include <cuda_runtime.h>
#include <cuda_bf16.h>
#include <math.h>
#include <stdint.h>

// Problem constants
#define B_ 2
#define T_ 2048
#define C_ 2048
#define H_ 16
#define D_ 128
#define M_ (B_ * T_)
#define ND_ (H_ * D_)

// ---------------------------------------------------------------------------
// Scratch
// ---------------------------------------------------------------------------
__device__ float g_q[(size_t)B_ * H_ * T_ * D_];   // (B,H,T,D)
__device__ float g_k[(size_t)B_ * H_ * T_ * D_];
__device__ float g_v[(size_t)B_ * H_ * T_ * D_];
__device__ float g_ao[(size_t)B_ * T_ * C_];       // attention out, (B,T,H*D)
__device__ float g_cos[T_ * (D_ / 2)];
__device__ float g_sin[T_ * (D_ / 2)];

// ---------------------------------------------------------------------------
// RoPE table
// ---------------------------------------------------------------------------
__global__ void rope_table_kernel() {
    int i = blockIdx.x * blockDim.x + threadIdx.x;
    if (i >= T_ * (D_ / 2)) return;
    int t  = i >> 6;
    int d2 = i & 63;
    float inv = powf(10000.0f, -((float)(2 * d2)) / (float)D_);
    float ang = (float)t * inv;
    g_cos[i] = cosf(ang);
    g_sin[i] = sinf(ang);
}

// ---------------------------------------------------------------------------
// mma.sync helpers (compute_103-safe: no tcgen05)
// ---------------------------------------------------------------------------
__device__ __forceinline__ uint32_t smem_u32(const void* p) {
    uint32_t a;
    asm("{ .reg .u64 t; cvta.to.shared.u64 t, %1; cvt.u32.u64 %0, t; }" : "=r"(a) : "l"(p));
    return a;
}
__device__ __forceinline__ void ldsm_x4(uint32_t* r, uint32_t addr) {
    asm volatile("ldmatrix.sync.aligned.m8n8.x4.shared.b16 {%0,%1,%2,%3}, [%4];"
                 : "=r"(r[0]), "=r"(r[1]), "=r"(r[2]), "=r"(r[3]) : "r"(addr));
}
__device__ __forceinline__ void ldsm_x4_t(uint32_t* r, uint32_t addr) {
    asm volatile("ldmatrix.sync.aligned.m8n8.x4.trans.shared.b16 {%0,%1,%2,%3}, [%4];"
                 : "=r"(r[0]), "=r"(r[1]), "=r"(r[2]), "=r"(r[3]) : "r"(addr));
}
__device__ __forceinline__ void mma_bf16(float* c, const uint32_t* a, const uint32_t* b) {
    asm volatile("mma.sync.aligned.m16n8k16.row.col.f32.bf16.bf16.f32 "
                 "{%0,%1,%2,%3}, {%4,%5,%6,%7}, {%8,%9}, {%0,%1,%2,%3};"
                 : "+f"(c[0]), "+f"(c[1]), "+f"(c[2]), "+f"(c[3])
                 : "r"(a[0]), "r"(a[1]), "r"(a[2]), "r"(a[3]), "r"(b[0]), "r"(b[1]));
}
__device__ __forceinline__ void cvt_hilo2(float x, float y, uint32_t& hi, uint32_t& lo) {
    __nv_bfloat16 hx = __float2bfloat16(x);
    __nv_bfloat16 hy = __float2bfloat16(y);
    __nv_bfloat16 lx = __float2bfloat16(x - __bfloat162float(hx));
    __nv_bfloat16 ly = __float2bfloat16(y - __bfloat162float(hy));
    hi = ((uint32_t)__bfloat16_as_ushort(hy) << 16) | __bfloat16_as_ushort(hx);
    lo = ((uint32_t)__bfloat16_as_ushort(ly) << 16) | __bfloat16_as_ushort(lx);
}
// exp2 on the FMA pipe (avoids MUFU bottleneck)
__device__ __forceinline__ float exp2p(float t) {
    t = fmaxf(t, -100.0f);
    float nf = rintf(t);
    float f = t - nf;
    float p =             1.3333558146e-3f;
    p = fmaf(p, f, 9.6181291076e-3f);
    p = fmaf(p, f, 5.5504108665e-2f);
    p = fmaf(p, f, 2.4022650696e-1f);
    p = fmaf(p, f, 6.9314718056e-1f);
    p = fmaf(p, f, 1.0f);
    float sc = __int_as_float(((int)nf + 127) << 23);
    return p * sc;
}

// ---------------------------------------------------------------------------
// bf16x3 GEMM via mma.sync; term-major MMA order (acc reuse distance = 16)
// ---------------------------------------------------------------------------
#define BK 32
#define A_LD 40
#define W_LD 136
#define A_TILE_H (128 * A_LD)
#define W_TILE_H (BK * W_LD)
#define BUF_BYTES ((2 * A_TILE_H + 2 * W_TILE_H) * 2)
#define GEMM_SMEM_BYTES (2 * BUF_BYTES)

template <int OP>
__global__ void __launch_bounds__(256, 1)
gemm_mma_kernel(const float* __restrict__ Aparam,
                const float* __restrict__ W,
                float* __restrict__ Cparam) {
    extern __shared__ char smem[];
    const uint32_t sb = smem_u32(smem);

    const float* A = (OP == 3) ? g_ao : Aparam;
    float* Cout = (OP == 0) ? g_q : (OP == 1) ? g_k : (OP == 2) ? g_v : Cparam;

    const int tid  = threadIdx.x;
    const int lane = tid & 31;
    const int wid  = tid >> 5;
    const int m0 = blockIdx.y * 128;
    const int n0 = blockIdx.x * 128;
    const int wm = (wid & 1) * 64;
    const int wn = (wid >> 1) * 32;

    float acc[4][4][4];
#pragma unroll
    for (int mt = 0; mt < 4; mt++)
#pragma unroll
        for (int nt = 0; nt < 4; nt++)
#pragma unroll
            for (int f = 0; f < 4; f++) acc[mt][nt][f] = 0.0f;

    const int a_row = tid >> 3;
    const int a_c4  = (tid & 7) * 4;
    const int w_krow = tid >> 5;
    const int w_n4   = (tid & 31) * 4;

    const int a_frag_off = (wm + (lane & 15)) * A_LD + (lane >> 4) * 8;
    const int b_frag_off = (lane & 15) * W_LD + wn + (lane >> 4) * 8;

    float4 ra[4], rw[4];
    {
        const float* Ab = A + (size_t)(m0 + a_row) * 2048 + a_c4;
#pragma unroll
        for (int it = 0; it < 4; it++) ra[it] = *(const float4*)(Ab + (size_t)it * 32 * 2048);
        const float* Wb = W + (size_t)w_krow * 2048 + n0 + w_n4;
#pragma unroll
        for (int it = 0; it < 4; it++) rw[it] = *(const float4*)(Wb + (size_t)it * 8 * 2048);
    }

#define STORE_STAGE(BUFI) do {                                                   \
    char* ahi_ = smem + (BUFI) * BUF_BYTES;                                      \
    char* alo_ = ahi_ + A_TILE_H * 2;                                            \
    char* whi_ = alo_ + A_TILE_H * 2;                                            \
    char* wlo_ = whi_ + W_TILE_H * 2;                                            \
    _Pragma("unroll")                                                            \
    for (int it = 0; it < 4; it++) {                                             \
        int row = a_row + 32 * it;                                               \
        uint32_t h01, l01, h23, l23;                                             \
        cvt_hilo2(ra[it].x, ra[it].y, h01, l01);                                 \
        cvt_hilo2(ra[it].z, ra[it].w, h23, l23);                                 \
        int off = (row * A_LD + a_c4) * 2;                                       \
        *(uint2*)(ahi_ + off) = make_uint2(h01, h23);                            \
        *(uint2*)(alo_ + off) = make_uint2(l01, l23);                            \
    }                                                                            \
    _Pragma("unroll")                                                            \
    for (int it = 0; it < 4; it++) {                                             \
        int kr = w_krow + 8 * it;                                                \
        uint32_t h01, l01, h23, l23;                                             \
        cvt_hilo2(rw[it].x, rw[it].y, h01, l01);                                 \
        cvt_hilo2(rw[it].z, rw[it].w, h23, l23);                                 \
        int off = (kr * W_LD + w_n4) * 2;                                        \
        *(uint2*)(whi_ + off) = make_uint2(h01, h23);                            \
        *(uint2*)(wlo_ + off) = make_uint2(l01, l23);                            \
    }                                                                            \
} while (0)

    STORE_STAGE(0);
    __syncthreads();

    const int NS = 2048 / BK;
    for (int s = 0; s < NS; s++) {
        const int buf = s & 1;
        if (s + 1 < NS) {
            const int k0 = (s + 1) * BK;
            const float* Ab = A + (size_t)(m0 + a_row) * 2048 + a_c4 + k0;
#pragma unroll
            for (int it = 0; it < 4; it++) ra[it] = *(const float4*)(Ab + (size_t)it * 32 * 2048);
            const float* Wb = W + (size_t)(k0 + w_krow) * 2048 + n0 + w_n4;
#pragma unroll
            for (int it = 0; it < 4; it++) rw[it] = *(const float4*)(Wb + (size_t)it * 8 * 2048);
        }

        const uint32_t ahi = sb + buf * BUF_BYTES;
        const uint32_t alo = ahi + A_TILE_H * 2;
        const uint32_t whi = alo + A_TILE_H * 2;
        const uint32_t wlo = whi + W_TILE_H * 2;

#pragma unroll
        for (int ks = 0; ks < 2; ks++) {
            uint32_t ah[4][4], al[4][4];
#pragma unroll
            for (int mt = 0; mt < 4; mt++) {
                uint32_t ao = (a_frag_off + mt * 16 * A_LD + ks * 16) * 2;
                ldsm_x4(ah[mt], ahi + ao);
                ldsm_x4(al[mt], alo + ao);
            }
            uint32_t bh[2][4], bl[2][4];
#pragma unroll
            for (int np = 0; np < 2; np++) {
                uint32_t bo = (b_frag_off + ks * 16 * W_LD + np * 16) * 2;
                ldsm_x4_t(bh[np], whi + bo);
                ldsm_x4_t(bl[np], wlo + bo);
            }
            // term-major: same accumulator revisited only after 16 other MMAs
#pragma unroll
            for (int mt = 0; mt < 4; mt++)
#pragma unroll
                for (int nt = 0; nt < 4; nt++)
                    mma_bf16(acc[mt][nt], ah[mt], &bh[nt >> 1][(nt & 1) * 2]);
#pragma unroll
            for (int mt = 0; mt < 4; mt++)
#pragma unroll
                for (int nt = 0; nt < 4; nt++)
                    mma_bf16(acc[mt][nt], ah[mt], &bl[nt >> 1][(nt & 1) * 2]);
#pragma unroll
            for (int mt = 0; mt < 4; mt++)
#pragma unroll
                for (int nt = 0; nt < 4; nt++)
                    mma_bf16(acc[mt][nt], al[mt], &bh[nt >> 1][(nt & 1) * 2]);
        }

        if (s + 1 < NS) STORE_STAGE(buf ^ 1);
        __syncthreads();
    }
#undef STORE_STAGE

    const int lrow = lane >> 2;
    const int lcol = (lane & 3) * 2;
    const int h = blockIdx.x;

#pragma unroll
    for (int mt = 0; mt < 4; mt++) {
#pragma unroll
        for (int rh = 0; rh < 2; rh++) {
            const int m = m0 + wm + mt * 16 + lrow + rh * 8;
            if (OP == 3) {
                float* dst = Cout + (size_t)m * ND_ + n0;
#pragma unroll
                for (int nt = 0; nt < 4; nt++) {
                    int d = wn + nt * 8 + lcol;
                    float x0 = acc[mt][nt][rh * 2 + 0];
                    float x1 = acc[mt][nt][rh * 2 + 1];
                    *(float2*)(dst + d) = make_float2(x0, x1);
                }
            } else {
                const int b = m >> 11;
                const int t = m & (T_ - 1);
                float* dst = Cout + (((size_t)(b * H_ + h) * T_ + t) << 7);
#pragma unroll
                for (int nt = 0; nt < 4; nt++) {
                    int d = wn + nt * 8 + lcol;
                    float x0 = acc[mt][nt][rh * 2 + 0];
                    float x1 = acc[mt][nt][rh * 2 + 1];
                    if (OP <= 1) {
                        float cs = g_cos[t * 64 + (d >> 1)];
                        float sn = g_sin[t * 64 + (d >> 1)];
                        *(float2*)(dst + d) = make_float2(x0 * cs - x1 * sn,
                                                          x0 * sn + x1 * cs);
                    } else {
                        *(float2*)(dst + d) = make_float2(x0, x1);
                    }
                }
            }
        }
    }
}

// ---------------------------------------------------------------------------
// Tensor-core flash attention, bf16x3 S and PV, term-major MMA ordering.
// ---------------------------------------------------------------------------
#define Q_LD 136
#define K_LD 136
#define V_LD 136
#define QHI_OFF 0
#define QLO_OFF (QHI_OFF + 128 * Q_LD * 2)
#define KHI_OFF (QLO_OFF + 128 * Q_LD * 2)
#define KLO_OFF (KHI_OFF + 64 * K_LD * 2)
#define VHI_OFF (KLO_OFF + 64 * K_LD * 2)
#define VLO_OFF (VHI_OFF + 64 * V_LD * 2)
#define ATT_SMEM (VLO_OFF + 64 * V_LD * 2)     // 139264

__global__ void __launch_bounds__(256, 1) attn_mma_kernel() {
    extern __shared__ char smc[];
    const uint32_t sb = smem_u32(smc);
    const int tid  = threadIdx.x;
    const int lane = tid & 31;
    const int wid  = tid >> 5;
    const int bh   = blockIdx.y;
    const int b    = bh >> 4;
    const int h    = bh & (H_ - 1);
    const int q0   = blockIdx.x * 128;
    const int wm   = wid * 16;
    const int lrow = lane >> 2;
    const int lcol2 = (lane & 3) * 2;

    const float* Qg = g_q + (size_t)bh * T_ * D_;
    const float* Kg = g_k + (size_t)bh * T_ * D_;
    const float* Vg = g_v + (size_t)bh * T_ * D_;

    // ---- load Q once: scale by log2(e)/sqrt(128), split hi/lo ----
    const float qs = 0.0883883476483184405f * 1.4426950408889634f;
    for (int it = 0; it < 16; it++) {
        int i  = it * 256 + tid;
        int r  = i >> 5;
        int c4 = (i & 31) * 4;
        float4 v = *(const float4*)(Qg + (size_t)(q0 + r) * D_ + c4);
        uint32_t h01, l01, h23, l23;
        cvt_hilo2(v.x * qs, v.y * qs, h01, l01);
        cvt_hilo2(v.z * qs, v.w * qs, h23, l23);
        int off = (r * Q_LD + c4) * 2;
        *(uint2*)(smc + QHI_OFF + off) = make_uint2(h01, h23);
        *(uint2*)(smc + QLO_OFF + off) = make_uint2(l01, l23);
    }

    const uint32_t aq_base = sb + QHI_OFF + ((wm + (lane & 15)) * Q_LD + (lane >> 4) * 8) * 2;
    const uint32_t aq_lo_d = QLO_OFF - QHI_OFF;
    const int kb_row = (lane & 7) + ((lane >> 4) << 3);
    const int kb_col = ((lane >> 3) & 1) << 3;
    const uint32_t kb_base = sb + KHI_OFF + (kb_row * K_LD + kb_col) * 2;
    const uint32_t kb_lo_d = KLO_OFF - KHI_OFF;
    const uint32_t vh_base = sb + VHI_OFF + ((lane & 15) * V_LD + (lane >> 4) * 8) * 2;
    const uint32_t vb_lo_d = VLO_OFF - VHI_OFF;

    float o[16][4];
#pragma unroll
    for (int dt = 0; dt < 16; dt++)
#pragma unroll
        for (int f = 0; f < 4; f++) o[dt][f] = 0.0f;
    float m0 = -1e30f, m1 = -1e30f, l0 = 0.0f, l1 = 0.0f;

    const int njt = 2 * blockIdx.x + 2;

    for (int jt = 0; jt < njt; jt++) {
        const int k0 = jt * 64;
        __syncthreads();
        // ---- load K (hi/lo) and V (hi/lo) tiles ----
        for (int it = 0; it < 8; it++) {
            int i  = it * 256 + tid;
            int r  = i >> 5;
            int c4 = (i & 31) * 4;
            float4 kv = *(const float4*)(Kg + (size_t)(k0 + r) * D_ + c4);
            uint32_t h01, l01, h23, l23;
            cvt_hilo2(kv.x, kv.y, h01, l01);
            cvt_hilo2(kv.z, kv.w, h23, l23);
            int off = (r * K_LD + c4) * 2;
            *(uint2*)(smc + KHI_OFF + off) = make_uint2(h01, h23);
            *(uint2*)(smc + KLO_OFF + off) = make_uint2(l01, l23);
            float4 vv = *(const float4*)(Vg + (size_t)(k0 + r) * D_ + c4);
            uint32_t vh01, vl01, vh23, vl23;
            cvt_hilo2(vv.x, vv.y, vh01, vl01);
            cvt_hilo2(vv.z, vv.w, vh23, vl23);
            int voff = (r * V_LD + c4) * 2;
            *(uint2*)(smc + VHI_OFF + voff) = make_uint2(vh01, vh23);
            *(uint2*)(smc + VLO_OFF + voff) = make_uint2(vl01, vl23);
        }
        __syncthreads();

        // ---- S = Q K^T (bf16x3, term-major: acc reuse distance 8) ----
        float s[8][4];
#pragma unroll
        for (int nt = 0; nt < 8; nt++)
#pragma unroll
            for (int f = 0; f < 4; f++) s[nt][f] = 0.0f;

#pragma unroll
        for (int ks = 0; ks < 8; ks++) {
            uint32_t ah[4], al[4];
            ldsm_x4(ah, aq_base + ks * 32);
            ldsm_x4(al, aq_base + aq_lo_d + ks * 32);
            uint32_t kh[4][4], kl[4][4];
#pragma unroll
            for (int np = 0; np < 4; np++) {
                uint32_t off = (uint32_t)(np * (16 * K_LD * 2) + ks * 32);
                ldsm_x4(kh[np], kb_base + off);
                ldsm_x4(kl[np], kb_base + kb_lo_d + off);
            }
#pragma unroll
            for (int np = 0; np < 4; np++) {
                mma_bf16(s[2 * np],     ah, kh[np]);
                mma_bf16(s[2 * np + 1], ah, kh[np] + 2);
            }
#pragma unroll
            for (int np = 0; np < 4; np++) {
                mma_bf16(s[2 * np],     ah, kl[np]);
                mma_bf16(s[2 * np + 1], ah, kl[np] + 2);
            }
#pragma unroll
            for (int np = 0; np < 4; np++) {
                mma_bf16(s[2 * np],     al, kh[np]);
                mma_bf16(s[2 * np + 1], al, kh[np] + 2);
            }
        }

        // ---- causal mask (diagonal tiles only) ----
        if (k0 + 63 > q0 + wm) {
            const int row0 = q0 + wm + lrow;
            const int row1 = row0 + 8;
#pragma unroll
            for (int nt = 0; nt < 8; nt++) {
                int c0 = k0 + nt * 8 + lcol2;
                if (c0 > row0)     s[nt][0] = -1e30f;
                if (c0 + 1 > row0) s[nt][1] = -1e30f;
                if (c0 > row1)     s[nt][2] = -1e30f;
                if (c0 + 1 > row1) s[nt][3] = -1e30f;
            }
        }

        // ---- online softmax (base 2) ----
        float mx0 = -1e30f, mx1 = -1e30f;
#pragma unroll
        for (int nt = 0; nt < 8; nt++) {
            mx0 = fmaxf(mx0, fmaxf(s[nt][0], s[nt][1]));
            mx1 = fmaxf(mx1, fmaxf(s[nt][2], s[nt][3]));
        }
        mx0 = fmaxf(mx0, __shfl_xor_sync(0xffffffffu, mx0, 1));
        mx0 = fmaxf(mx0, __shfl_xor_sync(0xffffffffu, mx0, 2));
        mx1 = fmaxf(mx1, __shfl_xor_sync(0xffffffffu, mx1, 1));
        mx1 = fmaxf(mx1, __shfl_xor_sync(0xffffffffu, mx1, 2));
        float m0n = fmaxf(m0, mx0);
        float m1n = fmaxf(m1, mx1);
        float corr0 = exp2p(m0 - m0n);
        float corr1 = exp2p(m1 - m1n);
        m0 = m0n; m1 = m1n;

        uint32_t ph01[8], ph23[8], pl01[8], pl23[8];
        float sum0 = 0.0f, sum1 = 0.0f;
#pragma unroll
        for (int nt = 0; nt < 8; nt++) {
            float p0 = exp2p(s[nt][0] - m0);
            float p1 = exp2p(s[nt][1] - m0);
            float p2 = exp2p(s[nt][2] - m1);
            float p3 = exp2p(s[nt][3] - m1);
            sum0 += p0 + p1;
            sum1 += p2 + p3;
            cvt_hilo2(p0, p1, ph01[nt], pl01[nt]);
            cvt_hilo2(p2, p3, ph23[nt], pl23[nt]);
        }
        sum0 += __shfl_xor_sync(0xffffffffu, sum0, 1);
        sum0 += __shfl_xor_sync(0xffffffffu, sum0, 2);
        sum1 += __shfl_xor_sync(0xffffffffu, sum1, 1);
        sum1 += __shfl_xor_sync(0xffffffffu, sum1, 2);
        l0 = l0 * corr0 + sum0;
        l1 = l1 * corr1 + sum1;

#pragma unroll
        for (int dt = 0; dt < 16; dt++) {
            o[dt][0] *= corr0; o[dt][1] *= corr0;
            o[dt][2] *= corr1; o[dt][3] *= corr1;
        }

        // ---- O += P V (bf16x3, term-major in np-chunks of 4: distance 8) ----
#pragma unroll
        for (int ks = 0; ks < 4; ks++) {
            uint32_t aph[4] = { ph01[2 * ks], ph23[2 * ks], ph01[2 * ks + 1], ph23[2 * ks + 1] };
            uint32_t apl[4] = { pl01[2 * ks], pl23[2 * ks], pl01[2 * ks + 1], pl23[2 * ks + 1] };
#pragma unroll
            for (int half = 0; half < 2; half++) {
                uint32_t vh[4][4], vl[4][4];
#pragma unroll
                for (int j = 0; j < 4; j++) {
                    int np = half * 4 + j;
                    uint32_t off = (uint32_t)(ks * (16 * V_LD * 2) + np * 32);
                    ldsm_x4_t(vh[j], vh_base + off);
                    ldsm_x4_t(vl[j], vh_base + vb_lo_d + off);
                }
#pragma unroll
                for (int j = 0; j < 4; j++) {
                    int np = half * 4 + j;
                    mma_bf16(o[2 * np],     aph, vh[j]);
                    mma_bf16(o[2 * np + 1], aph, vh[j] + 2);
                }
#pragma unroll
                for (int j = 0; j < 4; j++) {
                    int np = half * 4 + j;
                    mma_bf16(o[2 * np],     aph, vl[j]);
                    mma_bf16(o[2 * np + 1], aph, vl[j] + 2);
                }
#pragma unroll
                for (int j = 0; j < 4; j++) {
                    int np = half * 4 + j;
                    mma_bf16(o[2 * np],     apl, vh[j]);
                    mma_bf16(o[2 * np + 1], apl, vh[j] + 2);
                }
            }
        }
    }

    // ---- epilogue: normalize, store to (B,T,H*D) ----
    const float inv0 = 1.0f / l0;
    const float inv1 = 1.0f / l1;
    const int row0 = q0 + wm + lrow;
    const int row1 = row0 + 8;
    float* dst0 = g_ao + (size_t)(b * T_ + row0) * C_ + h * D_;
    float* dst1 = g_ao + (size_t)(b * T_ + row1) * C_ + h * D_;
#pragma unroll
    for (int dt = 0; dt < 16; dt++) {
        int d = dt * 8 + lcol2;
        *(float2*)(dst0 + d) = make_float2(o[dt][0] * inv0, o[dt][1] * inv0);
        *(float2*)(dst1 + d) = make_float2(o[dt][2] * inv1, o[dt][3] * inv1);
    }
}

// ---------------------------------------------------------------------------
// Launch
// ---------------------------------------------------------------------------
extern "C" void kernel_launch(void* const* d_in, const int* in_sizes, int n_in,
                              void* d_out, int out_size) {
    const float* x  = (const float*)d_in[0];
    const float* wq = (const float*)d_in[2];
    const float* wk = (const float*)d_in[3];
    const float* wv = (const float*)d_in[4];
    const float* wo = (const float*)d_in[5];
    float* out = (float*)d_out;

    rope_table_kernel<<<(T_ * (D_ / 2) + 255) / 256, 256>>>();

    cudaFuncSetAttribute(gemm_mma_kernel<0>, cudaFuncAttributeMaxDynamicSharedMemorySize, GEMM_SMEM_BYTES);
    cudaFuncSetAttribute(gemm_mma_kernel<1>, cudaFuncAttributeMaxDynamicSharedMemorySize, GEMM_SMEM_BYTES);
    cudaFuncSetAttribute(gemm_mma_kernel<2>, cudaFuncAttributeMaxDynamicSharedMemorySize, GEMM_SMEM_BYTES);
    cudaFuncSetAttribute(gemm_mma_kernel<3>, cudaFuncAttributeMaxDynamicSharedMemorySize, GEMM_SMEM_BYTES);
    cudaFuncSetAttribute(attn_mma_kernel,    cudaFuncAttributeMaxDynamicSharedMemorySize, ATT_SMEM);

    dim3 gg(ND_ / 128, M_ / 128);  // (16, 32)
    gemm_mma_kernel<0><<<gg, 256, GEMM_SMEM_BYTES>>>(x, wq, nullptr);
    gemm_mma_kernel<1><<<gg, 256, GEMM_SMEM_BYTES>>>(x, wk, nullptr);
    gemm_mma_kernel<2><<<gg, 256, GEMM_SMEM_BYTES>>>(x, wv, nullptr);

    attn_mma_kernel<<<dim3(T_ / 128, B_ * H_), 256, ATT_SMEM>>>();

    gemm_mma_kernel<3><<<gg, 256, GEMM_SMEM_BYTES>>>(nullptr, wo, out);
}

// round 7
// speedup vs baseline: 3.4799x; 1.2730x over previous
#include <cuda_runtime.h>
#include <cuda_bf16.h>
#include <math.h>
#include <stdint.h>

// Problem constants
#define B_ 2
#define T_ 2048
#define C_ 2048
#define H_ 16
#define D_ 128
#define M_ (B_ * T_)
#define ND_ (H_ * D_)

// ---------------------------------------------------------------------------
// Scratch: bf16 hi/lo pairs everywhere (split once, use many times)
// ---------------------------------------------------------------------------
__device__ __nv_bfloat16 gx_hi[(size_t)M_ * C_],  gx_lo[(size_t)M_ * C_];
__device__ __nv_bfloat16 gwq_hi[(size_t)C_ * ND_], gwq_lo[(size_t)C_ * ND_];
__device__ __nv_bfloat16 gwk_hi[(size_t)C_ * ND_], gwk_lo[(size_t)C_ * ND_];
__device__ __nv_bfloat16 gwv_hi[(size_t)C_ * ND_], gwv_lo[(size_t)C_ * ND_];
__device__ __nv_bfloat16 gwo_hi[(size_t)C_ * ND_], gwo_lo[(size_t)C_ * ND_];
__device__ __nv_bfloat16 gq_hi[(size_t)B_ * H_ * T_ * D_], gq_lo[(size_t)B_ * H_ * T_ * D_];
__device__ __nv_bfloat16 gk_hi[(size_t)B_ * H_ * T_ * D_], gk_lo[(size_t)B_ * H_ * T_ * D_];
__device__ __nv_bfloat16 gv_hi[(size_t)B_ * H_ * T_ * D_], gv_lo[(size_t)B_ * H_ * T_ * D_];
__device__ __nv_bfloat16 gao_hi[(size_t)M_ * C_], gao_lo[(size_t)M_ * C_];
__device__ float g_cos[T_ * (D_ / 2)];
__device__ float g_sin[T_ * (D_ / 2)];

// ---------------------------------------------------------------------------
// Helpers
// ---------------------------------------------------------------------------
__device__ __forceinline__ uint32_t smem_u32(const void* p) {
    uint32_t a;
    asm("{ .reg .u64 t; cvta.to.shared.u64 t, %1; cvt.u32.u64 %0, t; }" : "=r"(a) : "l"(p));
    return a;
}
__device__ __forceinline__ void ldsm_x4(uint32_t* r, uint32_t addr) {
    asm volatile("ldmatrix.sync.aligned.m8n8.x4.shared.b16 {%0,%1,%2,%3}, [%4];"
                 : "=r"(r[0]), "=r"(r[1]), "=r"(r[2]), "=r"(r[3]) : "r"(addr));
}
__device__ __forceinline__ void ldsm_x4_t(uint32_t* r, uint32_t addr) {
    asm volatile("ldmatrix.sync.aligned.m8n8.x4.trans.shared.b16 {%0,%1,%2,%3}, [%4];"
                 : "=r"(r[0]), "=r"(r[1]), "=r"(r[2]), "=r"(r[3]) : "r"(addr));
}
__device__ __forceinline__ void mma_bf16(float* c, const uint32_t* a, const uint32_t* b) {
    asm volatile("mma.sync.aligned.m16n8k16.row.col.f32.bf16.bf16.f32 "
                 "{%0,%1,%2,%3}, {%4,%5,%6,%7}, {%8,%9}, {%0,%1,%2,%3};"
                 : "+f"(c[0]), "+f"(c[1]), "+f"(c[2]), "+f"(c[3])
                 : "r"(a[0]), "r"(a[1]), "r"(a[2]), "r"(a[3]), "r"(b[0]), "r"(b[1]));
}
__device__ __forceinline__ void cvt_hilo2(float x, float y, uint32_t& hi, uint32_t& lo) {
    __nv_bfloat16 hx = __float2bfloat16(x);
    __nv_bfloat16 hy = __float2bfloat16(y);
    __nv_bfloat16 lx = __float2bfloat16(x - __bfloat162float(hx));
    __nv_bfloat16 ly = __float2bfloat16(y - __bfloat162float(hy));
    hi = ((uint32_t)__bfloat16_as_ushort(hy) << 16) | __bfloat16_as_ushort(hx);
    lo = ((uint32_t)__bfloat16_as_ushort(ly) << 16) | __bfloat16_as_ushort(lx);
}
__device__ __forceinline__ void cp16(uint32_t dst, const void* src) {
    asm volatile("cp.async.cg.shared.global [%0], [%1], 16;" :: "r"(dst), "l"(src));
}
__device__ __forceinline__ void cp_commit() {
    asm volatile("cp.async.commit_group;" ::: "memory");
}
template <int N>
__device__ __forceinline__ void cp_wait() {
    asm volatile("cp.async.wait_group %0;" :: "n"(N) : "memory");
}
// exp2 on the FMA pipe
__device__ __forceinline__ float exp2p(float t) {
    t = fmaxf(t, -100.0f);
    float nf = rintf(t);
    float f = t - nf;
    float p =             1.3333558146e-3f;
    p = fmaf(p, f, 9.6181291076e-3f);
    p = fmaf(p, f, 5.5504108665e-2f);
    p = fmaf(p, f, 2.4022650696e-1f);
    p = fmaf(p, f, 6.9314718056e-1f);
    p = fmaf(p, f, 1.0f);
    float sc = __int_as_float(((int)nf + 127) << 23);
    return p * sc;
}

// ---------------------------------------------------------------------------
// RoPE table + one-time fp32 -> bf16 hi/lo split
// ---------------------------------------------------------------------------
__global__ void rope_table_kernel() {
    int i = blockIdx.x * blockDim.x + threadIdx.x;
    if (i >= T_ * (D_ / 2)) return;
    int t  = i >> 6;
    int d2 = i & 63;
    float inv = powf(10000.0f, -((float)(2 * d2)) / (float)D_);
    float ang = (float)t * inv;
    g_cos[i] = cosf(ang);
    g_sin[i] = sinf(ang);
}

__global__ void split_kernel(const float* __restrict__ src, int tgt, int n) {
    __nv_bfloat16 *hi, *lo;
    switch (tgt) {
        case 0: hi = gx_hi;  lo = gx_lo;  break;
        case 1: hi = gwq_hi; lo = gwq_lo; break;
        case 2: hi = gwk_hi; lo = gwk_lo; break;
        case 3: hi = gwv_hi; lo = gwv_lo; break;
        default: hi = gwo_hi; lo = gwo_lo; break;
    }
    int i = (blockIdx.x * blockDim.x + threadIdx.x) * 4;
    if (i >= n) return;
    float4 v = *(const float4*)(src + i);
    uint32_t h01, l01, h23, l23;
    cvt_hilo2(v.x, v.y, h01, l01);
    cvt_hilo2(v.z, v.w, h23, l23);
    *(uint2*)(hi + i) = make_uint2(h01, h23);
    *(uint2*)(lo + i) = make_uint2(l01, l23);
}

// ---------------------------------------------------------------------------
// bf16x3 GEMM, cp.async 3-stage pipeline, 2 CTAs/SM.
// Tile 128x128, BK=32. A: [row][k] pad to 80B/row. W: [k][n] pad 272B/row.
// OP: 0 Q(+RoPE,+qs -> gq) 1 K(+RoPE -> gk) 2 V(-> gv) 3 out (gao@wo -> Cout)
// ---------------------------------------------------------------------------
#define ST_ALO 10240
#define ST_WHI 20480
#define ST_WLO 29184
#define ST_STRIDE 37888
#define GEMM_SMEM (3 * ST_STRIDE)   // 113664

template <int OP>
__global__ void __launch_bounds__(256, 2)
gemm_mma_kernel(float* __restrict__ Cout) {
    extern __shared__ char smem[];
    const uint32_t sb = smem_u32(smem);
    const int tid  = threadIdx.x;
    const int lane = tid & 31;
    const int wid  = tid >> 5;
    const int m0 = blockIdx.y * 128;
    const int n0 = blockIdx.x * 128;
    const int wm = (wid & 1) * 64;
    const int wn = (wid >> 1) * 32;

    const __nv_bfloat16 *Ahi, *Alo, *Whi, *Wlo;
    if      (OP == 0) { Ahi = gx_hi;  Alo = gx_lo;  Whi = gwq_hi; Wlo = gwq_lo; }
    else if (OP == 1) { Ahi = gx_hi;  Alo = gx_lo;  Whi = gwk_hi; Wlo = gwk_lo; }
    else if (OP == 2) { Ahi = gx_hi;  Alo = gx_lo;  Whi = gwv_hi; Wlo = gwv_lo; }
    else              { Ahi = gao_hi; Alo = gao_lo; Whi = gwo_hi; Wlo = gwo_lo; }

    float acc[4][4][4];
#pragma unroll
    for (int mt = 0; mt < 4; mt++)
#pragma unroll
        for (int nt = 0; nt < 4; nt++)
#pragma unroll
            for (int f = 0; f < 4; f++) acc[mt][nt][f] = 0.0f;

    // ldsm per-thread base byte offsets
    const uint32_t a_frag = (wm + (lane & 15)) * 80 + (lane >> 4) * 16;
    const uint32_t b_frag = (lane & 15) * 272 + wn * 2 + (lane >> 4) * 16;

    // cp.async issue for stage s into slot s%3
    auto issue = [&](int s) {
        const int k0 = s * 32;
        const uint32_t st = sb + (s % 3) * ST_STRIDE;
#pragma unroll
        for (int i = 0; i < 2; i++) {
            int c = tid + i * 256;
            int row = c >> 2, cc = c & 3;
            size_t g = (size_t)(m0 + row) * 2048 + k0 + cc * 8;
            uint32_t d = st + row * 80 + cc * 16;
            cp16(d, Ahi + g);
            cp16(d + ST_ALO, Alo + g);
        }
#pragma unroll
        for (int i = 0; i < 2; i++) {
            int c = tid + i * 256;
            int row = c >> 4, cc = c & 15;
            size_t g = (size_t)(k0 + row) * 2048 + n0 + cc * 8;
            uint32_t d = st + ST_WHI + row * 272 + cc * 16;
            cp16(d, Whi + g);
            cp16(d + (ST_WLO - ST_WHI), Wlo + g);
        }
    };

    issue(0); cp_commit();
    issue(1); cp_commit();

    const int NS = 64;
    for (int s = 0; s < NS; s++) {
        if (s + 2 < NS) issue(s + 2);
        cp_commit();
        cp_wait<2>();
        __syncthreads();

        const uint32_t base = sb + (s % 3) * ST_STRIDE;
        const uint32_t ahi = base;
        const uint32_t alo = base + ST_ALO;
        const uint32_t whi = base + ST_WHI;
        const uint32_t wlo = base + ST_WLO;

#pragma unroll
        for (int ks = 0; ks < 2; ks++) {
            uint32_t ah[4][4], al[4][4];
#pragma unroll
            for (int mt = 0; mt < 4; mt++) {
                uint32_t ao = a_frag + mt * 1280 + ks * 32;
                ldsm_x4(ah[mt], ahi + ao);
                ldsm_x4(al[mt], alo + ao);
            }
            uint32_t bh[2][4], bl[2][4];
#pragma unroll
            for (int np = 0; np < 2; np++) {
                uint32_t bo = b_frag + ks * 4352 + np * 32;
                ldsm_x4_t(bh[np], whi + bo);
                ldsm_x4_t(bl[np], wlo + bo);
            }
#pragma unroll
            for (int mt = 0; mt < 4; mt++)
#pragma unroll
                for (int nt = 0; nt < 4; nt++)
                    mma_bf16(acc[mt][nt], ah[mt], &bh[nt >> 1][(nt & 1) * 2]);
#pragma unroll
            for (int mt = 0; mt < 4; mt++)
#pragma unroll
                for (int nt = 0; nt < 4; nt++)
                    mma_bf16(acc[mt][nt], ah[mt], &bl[nt >> 1][(nt & 1) * 2]);
#pragma unroll
            for (int mt = 0; mt < 4; mt++)
#pragma unroll
                for (int nt = 0; nt < 4; nt++)
                    mma_bf16(acc[mt][nt], al[mt], &bh[nt >> 1][(nt & 1) * 2]);
        }
        __syncthreads();
    }

    // ---- epilogue ----
    const int lrow = lane >> 2;
    const int lcol = (lane & 3) * 2;
    const int h = blockIdx.x;
    const float QS = 0.0883883476483184405f * 1.4426950408889634f;

#pragma unroll
    for (int mt = 0; mt < 4; mt++) {
#pragma unroll
        for (int rh = 0; rh < 2; rh++) {
            const int m = m0 + wm + mt * 16 + lrow + rh * 8;
            if (OP == 3) {
                float* dst = Cout + (size_t)m * ND_ + n0;
#pragma unroll
                for (int nt = 0; nt < 4; nt++) {
                    int d = wn + nt * 8 + lcol;
                    *(float2*)(dst + d) = make_float2(acc[mt][nt][rh * 2 + 0],
                                                      acc[mt][nt][rh * 2 + 1]);
                }
            } else {
                const int b = m >> 11;
                const int t = m & (T_ - 1);
                const size_t rowoff = (((size_t)(b * H_ + h) * T_ + t) << 7);
                __nv_bfloat16* dhi;
                __nv_bfloat16* dlo;
                if      (OP == 0) { dhi = gq_hi + rowoff; dlo = gq_lo + rowoff; }
                else if (OP == 1) { dhi = gk_hi + rowoff; dlo = gk_lo + rowoff; }
                else              { dhi = gv_hi + rowoff; dlo = gv_lo + rowoff; }
#pragma unroll
                for (int nt = 0; nt < 4; nt++) {
                    int d = wn + nt * 8 + lcol;
                    float x0 = acc[mt][nt][rh * 2 + 0];
                    float x1 = acc[mt][nt][rh * 2 + 1];
                    float r0, r1;
                    if (OP <= 1) {
                        float cs = g_cos[t * 64 + (d >> 1)];
                        float sn = g_sin[t * 64 + (d >> 1)];
                        r0 = x0 * cs - x1 * sn;
                        r1 = x0 * sn + x1 * cs;
                        if (OP == 0) { r0 *= QS; r1 *= QS; }
                    } else {
                        r0 = x0; r1 = x1;
                    }
                    uint32_t hh, ll;
                    cvt_hilo2(r0, r1, hh, ll);
                    *(uint32_t*)(dhi + d) = hh;
                    *(uint32_t*)(dlo + d) = ll;
                }
            }
        }
    }
}

// ---------------------------------------------------------------------------
// Tensor-core flash attention: bf16 hi/lo inputs, cp.async double-buffered K/V.
// BM=128 q rows / CTA, 8 warps, BN=64, D=128. bf16x3 S and PV.
// ---------------------------------------------------------------------------
#define AQ_LO 34816
#define KV_OFF 69632
#define KV_STRIDE 69632
#define KV_KLO 17408
#define KV_VHI 34816
#define KV_VLO 52224
#define ATT_SMEM 208896

__global__ void __launch_bounds__(256, 1) attn_mma_kernel() {
    extern __shared__ char smc[];
    const uint32_t sb = smem_u32(smc);
    const int tid  = threadIdx.x;
    const int lane = tid & 31;
    const int wid  = tid >> 5;
    const int bh   = blockIdx.y;
    const int b    = bh >> 4;
    const int h    = bh & (H_ - 1);
    const int q0   = blockIdx.x * 128;
    const int wm   = wid * 16;
    const int lrow = lane >> 2;
    const int lcol2 = (lane & 3) * 2;

    const __nv_bfloat16* qhi = gq_hi + (size_t)bh * T_ * D_;
    const __nv_bfloat16* qlo = gq_lo + (size_t)bh * T_ * D_;
    const __nv_bfloat16* khi = gk_hi + (size_t)bh * T_ * D_;
    const __nv_bfloat16* klo = gk_lo + (size_t)bh * T_ * D_;
    const __nv_bfloat16* vhi = gv_hi + (size_t)bh * T_ * D_;
    const __nv_bfloat16* vlo = gv_lo + (size_t)bh * T_ * D_;

    // ---- issue Q load (group 0) ----
#pragma unroll
    for (int i = 0; i < 8; i++) {
        int c = tid + i * 256;
        int row = c >> 4, cc = c & 15;
        size_t g = (size_t)(q0 + row) * 128 + cc * 8;
        uint32_t d = sb + row * 272 + cc * 16;
        cp16(d, qhi + g);
        cp16(d + AQ_LO, qlo + g);
    }
    cp_commit();

    auto issue_kv = [&](int buf, int k0) {
        uint32_t base = sb + KV_OFF + buf * KV_STRIDE;
#pragma unroll
        for (int i = 0; i < 4; i++) {
            int c = tid + i * 256;
            int row = c >> 4, cc = c & 15;
            size_t g = (size_t)(k0 + row) * 128 + cc * 8;
            uint32_t d = base + row * 272 + cc * 16;
            cp16(d, khi + g);
            cp16(d + KV_KLO, klo + g);
            cp16(d + KV_VHI, vhi + g);
            cp16(d + KV_VLO, vlo + g);
        }
    };

    issue_kv(0, 0);
    cp_commit();

    // frag base byte offsets
    const uint32_t aq_frag = (wm + (lane & 15)) * 272 + (lane >> 4) * 16;
    const int kb_row = (lane & 7) + ((lane >> 4) << 3);
    const uint32_t kb_frag = kb_row * 272 + ((lane >> 3) & 1) * 16;
    const uint32_t vb_frag = (lane & 15) * 272 + (lane >> 4) * 16;

    float o[16][4];
#pragma unroll
    for (int dt = 0; dt < 16; dt++)
#pragma unroll
        for (int f = 0; f < 4; f++) o[dt][f] = 0.0f;
    float m0 = -1e30f, m1 = -1e30f, l0 = 0.0f, l1 = 0.0f;

    const int njt = 2 * blockIdx.x + 2;

    for (int jt = 0; jt < njt; jt++) {
        if (jt + 1 < njt) issue_kv((jt + 1) & 1, (jt + 1) * 64);
        cp_commit();
        cp_wait<1>();
        __syncthreads();

        const int k0 = jt * 64;
        const uint32_t kvb = sb + KV_OFF + (jt & 1) * KV_STRIDE;
        const uint32_t aqh = sb + aq_frag;
        const uint32_t kbh = kvb + kb_frag;
        const uint32_t vbh = kvb + KV_VHI + vb_frag;

        // ---- S = Q K^T (bf16x3) ----
        float s[8][4];
#pragma unroll
        for (int nt = 0; nt < 8; nt++)
#pragma unroll
            for (int f = 0; f < 4; f++) s[nt][f] = 0.0f;

#pragma unroll
        for (int ks = 0; ks < 8; ks++) {
            uint32_t ah[4], al[4];
            ldsm_x4(ah, aqh + ks * 32);
            ldsm_x4(al, aqh + AQ_LO + ks * 32);
            uint32_t kh[4][4], kl[4][4];
#pragma unroll
            for (int np = 0; np < 4; np++) {
                uint32_t off = np * 4352 + ks * 32;
                ldsm_x4(kh[np], kbh + off);
                ldsm_x4(kl[np], kbh + KV_KLO + off);
            }
#pragma unroll
            for (int np = 0; np < 4; np++) {
                mma_bf16(s[2 * np],     ah, kh[np]);
                mma_bf16(s[2 * np + 1], ah, kh[np] + 2);
            }
#pragma unroll
            for (int np = 0; np < 4; np++) {
                mma_bf16(s[2 * np],     ah, kl[np]);
                mma_bf16(s[2 * np + 1], ah, kl[np] + 2);
            }
#pragma unroll
            for (int np = 0; np < 4; np++) {
                mma_bf16(s[2 * np],     al, kh[np]);
                mma_bf16(s[2 * np + 1], al, kh[np] + 2);
            }
        }

        // ---- causal mask ----
        if (k0 + 63 > q0 + wm) {
            const int row0 = q0 + wm + lrow;
            const int row1 = row0 + 8;
#pragma unroll
            for (int nt = 0; nt < 8; nt++) {
                int c0 = k0 + nt * 8 + lcol2;
                if (c0 > row0)     s[nt][0] = -1e30f;
                if (c0 + 1 > row0) s[nt][1] = -1e30f;
                if (c0 > row1)     s[nt][2] = -1e30f;
                if (c0 + 1 > row1) s[nt][3] = -1e30f;
            }
        }

        // ---- online softmax (base 2) ----
        float mx0 = -1e30f, mx1 = -1e30f;
#pragma unroll
        for (int nt = 0; nt < 8; nt++) {
            mx0 = fmaxf(mx0, fmaxf(s[nt][0], s[nt][1]));
            mx1 = fmaxf(mx1, fmaxf(s[nt][2], s[nt][3]));
        }
        mx0 = fmaxf(mx0, __shfl_xor_sync(0xffffffffu, mx0, 1));
        mx0 = fmaxf(mx0, __shfl_xor_sync(0xffffffffu, mx0, 2));
        mx1 = fmaxf(mx1, __shfl_xor_sync(0xffffffffu, mx1, 1));
        mx1 = fmaxf(mx1, __shfl_xor_sync(0xffffffffu, mx1, 2));
        float m0n = fmaxf(m0, mx0);
        float m1n = fmaxf(m1, mx1);
        float corr0 = exp2p(m0 - m0n);
        float corr1 = exp2p(m1 - m1n);
        m0 = m0n; m1 = m1n;

        uint32_t ph01[8], ph23[8], pl01[8], pl23[8];
        float sum0 = 0.0f, sum1 = 0.0f;
#pragma unroll
        for (int nt = 0; nt < 8; nt++) {
            float p0 = exp2p(s[nt][0] - m0);
            float p1 = exp2p(s[nt][1] - m0);
            float p2 = exp2p(s[nt][2] - m1);
            float p3 = exp2p(s[nt][3] - m1);
            sum0 += p0 + p1;
            sum1 += p2 + p3;
            cvt_hilo2(p0, p1, ph01[nt], pl01[nt]);
            cvt_hilo2(p2, p3, ph23[nt], pl23[nt]);
        }
        sum0 += __shfl_xor_sync(0xffffffffu, sum0, 1);
        sum0 += __shfl_xor_sync(0xffffffffu, sum0, 2);
        sum1 += __shfl_xor_sync(0xffffffffu, sum1, 1);
        sum1 += __shfl_xor_sync(0xffffffffu, sum1, 2);
        l0 = l0 * corr0 + sum0;
        l1 = l1 * corr1 + sum1;

#pragma unroll
        for (int dt = 0; dt < 16; dt++) {
            o[dt][0] *= corr0; o[dt][1] *= corr0;
            o[dt][2] *= corr1; o[dt][3] *= corr1;
        }

        // ---- O += P V (bf16x3) ----
#pragma unroll
        for (int ks = 0; ks < 4; ks++) {
            uint32_t aph[4] = { ph01[2 * ks], ph23[2 * ks], ph01[2 * ks + 1], ph23[2 * ks + 1] };
            uint32_t apl[4] = { pl01[2 * ks], pl23[2 * ks], pl01[2 * ks + 1], pl23[2 * ks + 1] };
#pragma unroll
            for (int half = 0; half < 2; half++) {
                uint32_t vh[4][4], vl[4][4];
#pragma unroll
                for (int j = 0; j < 4; j++) {
                    int np = half * 4 + j;
                    uint32_t off = ks * 4352 + np * 32;
                    ldsm_x4_t(vh[j], vbh + off);
                    ldsm_x4_t(vl[j], vbh + (KV_VLO - KV_VHI) + off);
                }
#pragma unroll
                for (int j = 0; j < 4; j++) {
                    int np = half * 4 + j;
                    mma_bf16(o[2 * np],     aph, vh[j]);
                    mma_bf16(o[2 * np + 1], aph, vh[j] + 2);
                }
#pragma unroll
                for (int j = 0; j < 4; j++) {
                    int np = half * 4 + j;
                    mma_bf16(o[2 * np],     aph, vl[j]);
                    mma_bf16(o[2 * np + 1], aph, vl[j] + 2);
                }
#pragma unroll
                for (int j = 0; j < 4; j++) {
                    int np = half * 4 + j;
                    mma_bf16(o[2 * np],     apl, vh[j]);
                    mma_bf16(o[2 * np + 1], apl, vh[j] + 2);
                }
            }
        }
        __syncthreads();
    }

    // ---- epilogue: normalize, split hi/lo, store to gao ----
    const float inv0 = 1.0f / l0;
    const float inv1 = 1.0f / l1;
    const int row0 = q0 + wm + lrow;
    const int row1 = row0 + 8;
    const size_t o0 = (size_t)(b * T_ + row0) * C_ + h * D_;
    const size_t o1 = (size_t)(b * T_ + row1) * C_ + h * D_;
#pragma unroll
    for (int dt = 0; dt < 16; dt++) {
        int d = dt * 8 + lcol2;
        uint32_t hh, ll;
        cvt_hilo2(o[dt][0] * inv0, o[dt][1] * inv0, hh, ll);
        *(uint32_t*)(gao_hi + o0 + d) = hh;
        *(uint32_t*)(gao_lo + o0 + d) = ll;
        cvt_hilo2(o[dt][2] * inv1, o[dt][3] * inv1, hh, ll);
        *(uint32_t*)(gao_hi + o1 + d) = hh;
        *(uint32_t*)(gao_lo + o1 + d) = ll;
    }
}

// ---------------------------------------------------------------------------
// Launch
// ---------------------------------------------------------------------------
extern "C" void kernel_launch(void* const* d_in, const int* in_sizes, int n_in,
                              void* d_out, int out_size) {
    const float* x  = (const float*)d_in[0];
    const float* wq = (const float*)d_in[2];
    const float* wk = (const float*)d_in[3];
    const float* wv = (const float*)d_in[4];
    const float* wo = (const float*)d_in[5];
    float* out = (float*)d_out;

    rope_table_kernel<<<(T_ * (D_ / 2) + 255) / 256, 256>>>();

    const int nx = M_ * C_;     // 8388608
    const int nw = C_ * ND_;    // 4194304
    split_kernel<<<nx / 1024, 256>>>(x,  0, nx);
    split_kernel<<<nw / 1024, 256>>>(wq, 1, nw);
    split_kernel<<<nw / 1024, 256>>>(wk, 2, nw);
    split_kernel<<<nw / 1024, 256>>>(wv, 3, nw);
    split_kernel<<<nw / 1024, 256>>>(wo, 4, nw);

    cudaFuncSetAttribute(gemm_mma_kernel<0>, cudaFuncAttributeMaxDynamicSharedMemorySize, GEMM_SMEM);
    cudaFuncSetAttribute(gemm_mma_kernel<1>, cudaFuncAttributeMaxDynamicSharedMemorySize, GEMM_SMEM);
    cudaFuncSetAttribute(gemm_mma_kernel<2>, cudaFuncAttributeMaxDynamicSharedMemorySize, GEMM_SMEM);
    cudaFuncSetAttribute(gemm_mma_kernel<3>, cudaFuncAttributeMaxDynamicSharedMemorySize, GEMM_SMEM);
    cudaFuncSetAttribute(attn_mma_kernel,    cudaFuncAttributeMaxDynamicSharedMemorySize, ATT_SMEM);

    dim3 gg(ND_ / 128, M_ / 128);  // (16, 32)
    gemm_mma_kernel<0><<<gg, 256, GEMM_SMEM>>>(nullptr);
    gemm_mma_kernel<1><<<gg, 256, GEMM_SMEM>>>(nullptr);
    gemm_mma_kernel<2><<<gg, 256, GEMM_SMEM>>>(nullptr);

    attn_mma_kernel<<<dim3(T_ / 128, B_ * H_), 256, ATT_SMEM>>>();

    gemm_mma_kernel<3><<<gg, 256, GEMM_SMEM>>>(out);
}

// round 8
// speedup vs baseline: 3.6122x; 1.0380x over previous
#include <cuda_runtime.h>
#include <cuda_bf16.h>
#include <cuda_fp16.h>
#include <math.h>
#include <stdint.h>

// Problem constants
#define B_ 2
#define T_ 2048
#define C_ 2048
#define H_ 16
#define D_ 128
#define M_ (B_ * T_)
#define ND_ (H_ * D_)
#define NX_ ((size_t)M_ * C_)
#define NW_ ((size_t)C_ * ND_)

// ---------------------------------------------------------------------------
// Scratch: bf16 hi/lo pairs (split once, use many times); V in fp16 hi/lo.
// ---------------------------------------------------------------------------
__device__ __nv_bfloat16 gx_hi[NX_],  gx_lo[NX_];
__device__ __nv_bfloat16 gwq_hi[NW_], gwq_lo[NW_];
__device__ __nv_bfloat16 gwk_hi[NW_], gwk_lo[NW_];
__device__ __nv_bfloat16 gwv_hi[NW_], gwv_lo[NW_];
__device__ __nv_bfloat16 gwo_hi[NW_], gwo_lo[NW_];
__device__ __nv_bfloat16 gq_hi[(size_t)B_ * H_ * T_ * D_], gq_lo[(size_t)B_ * H_ * T_ * D_];
__device__ __nv_bfloat16 gk_hi[(size_t)B_ * H_ * T_ * D_], gk_lo[(size_t)B_ * H_ * T_ * D_];
__device__ __half        gv_hi[(size_t)B_ * H_ * T_ * D_], gv_lo[(size_t)B_ * H_ * T_ * D_];
__device__ __nv_bfloat16 gao_hi[NX_], gao_lo[NX_];
__device__ float g_cos[T_ * (D_ / 2)];
__device__ float g_sin[T_ * (D_ / 2)];

// ---------------------------------------------------------------------------
// Helpers
// ---------------------------------------------------------------------------
__device__ __forceinline__ uint32_t smem_u32(const void* p) {
    uint32_t a;
    asm("{ .reg .u64 t; cvta.to.shared.u64 t, %1; cvt.u32.u64 %0, t; }" : "=r"(a) : "l"(p));
    return a;
}
__device__ __forceinline__ void ldsm_x4(uint32_t* r, uint32_t addr) {
    asm volatile("ldmatrix.sync.aligned.m8n8.x4.shared.b16 {%0,%1,%2,%3}, [%4];"
                 : "=r"(r[0]), "=r"(r[1]), "=r"(r[2]), "=r"(r[3]) : "r"(addr));
}
__device__ __forceinline__ void ldsm_x4_t(uint32_t* r, uint32_t addr) {
    asm volatile("ldmatrix.sync.aligned.m8n8.x4.trans.shared.b16 {%0,%1,%2,%3}, [%4];"
                 : "=r"(r[0]), "=r"(r[1]), "=r"(r[2]), "=r"(r[3]) : "r"(addr));
}
__device__ __forceinline__ void mma_bf16(float* c, const uint32_t* a, const uint32_t* b) {
    asm volatile("mma.sync.aligned.m16n8k16.row.col.f32.bf16.bf16.f32 "
                 "{%0,%1,%2,%3}, {%4,%5,%6,%7}, {%8,%9}, {%0,%1,%2,%3};"
                 : "+f"(c[0]), "+f"(c[1]), "+f"(c[2]), "+f"(c[3])
                 : "r"(a[0]), "r"(a[1]), "r"(a[2]), "r"(a[3]), "r"(b[0]), "r"(b[1]));
}
__device__ __forceinline__ void mma_f16(float* c, const uint32_t* a, const uint32_t* b) {
    asm volatile("mma.sync.aligned.m16n8k16.row.col.f32.f16.f16.f32 "
                 "{%0,%1,%2,%3}, {%4,%5,%6,%7}, {%8,%9}, {%0,%1,%2,%3};"
                 : "+f"(c[0]), "+f"(c[1]), "+f"(c[2]), "+f"(c[3])
                 : "r"(a[0]), "r"(a[1]), "r"(a[2]), "r"(a[3]), "r"(b[0]), "r"(b[1]));
}
__device__ __forceinline__ void cvt_hilo2(float x, float y, uint32_t& hi, uint32_t& lo) {
    __nv_bfloat16 hx = __float2bfloat16(x);
    __nv_bfloat16 hy = __float2bfloat16(y);
    __nv_bfloat16 lx = __float2bfloat16(x - __bfloat162float(hx));
    __nv_bfloat16 ly = __float2bfloat16(y - __bfloat162float(hy));
    hi = ((uint32_t)__bfloat16_as_ushort(hy) << 16) | __bfloat16_as_ushort(hx);
    lo = ((uint32_t)__bfloat16_as_ushort(ly) << 16) | __bfloat16_as_ushort(lx);
}
__device__ __forceinline__ void cvt_hilo2_f16(float x, float y, uint32_t& hi, uint32_t& lo) {
    __half hx = __float2half(x);
    __half hy = __float2half(y);
    __half lx = __float2half(x - __half2float(hx));
    __half ly = __float2half(y - __half2float(hy));
    hi = ((uint32_t)__half_as_ushort(hy) << 16) | __half_as_ushort(hx);
    lo = ((uint32_t)__half_as_ushort(ly) << 16) | __half_as_ushort(lx);
}
__device__ __forceinline__ uint32_t pack_f16x2(float lo, float hi) {
    uint32_t r;
    asm("cvt.rn.f16x2.f32 %0, %1, %2;" : "=r"(r) : "f"(hi), "f"(lo));
    return r;
}
__device__ __forceinline__ void cp16(uint32_t dst, const void* src) {
    asm volatile("cp.async.cg.shared.global [%0], [%1], 16;" :: "r"(dst), "l"(src));
}
__device__ __forceinline__ void cp_commit() {
    asm volatile("cp.async.commit_group;" ::: "memory");
}
template <int N>
__device__ __forceinline__ void cp_wait() {
    asm volatile("cp.async.wait_group %0;" :: "n"(N) : "memory");
}
// exp2 on the FMA pipe
__device__ __forceinline__ float exp2p(float t) {
    t = fmaxf(t, -100.0f);
    float nf = rintf(t);
    float f = t - nf;
    float p =             1.3333558146e-3f;
    p = fmaf(p, f, 9.6181291076e-3f);
    p = fmaf(p, f, 5.5504108665e-2f);
    p = fmaf(p, f, 2.4022650696e-1f);
    p = fmaf(p, f, 6.9314718056e-1f);
    p = fmaf(p, f, 1.0f);
    float sc = __int_as_float(((int)nf + 127) << 23);
    return p * sc;
}

// ---------------------------------------------------------------------------
// RoPE table + fused one-time fp32 -> bf16 hi/lo split (single launch)
// ---------------------------------------------------------------------------
__global__ void rope_table_kernel() {
    int i = blockIdx.x * blockDim.x + threadIdx.x;
    if (i >= T_ * (D_ / 2)) return;
    int t  = i >> 6;
    int d2 = i & 63;
    float inv = powf(10000.0f, -((float)(2 * d2)) / (float)D_);
    float ang = (float)t * inv;
    g_cos[i] = cosf(ang);
    g_sin[i] = sinf(ang);
}

__global__ void split_all_kernel(const float* __restrict__ x,
                                 const float* __restrict__ wq,
                                 const float* __restrict__ wk,
                                 const float* __restrict__ wv,
                                 const float* __restrict__ wo) {
    size_t idx = ((size_t)blockIdx.x * blockDim.x + threadIdx.x) * 4;
    const float* src;
    __nv_bfloat16 *hi, *lo;
    size_t base;
    if (idx < NX_) {
        src = x; hi = gx_hi; lo = gx_lo; base = idx;
    } else {
        size_t w = idx - NX_;
        int which = (int)(w >> 22);       // NW_ = 2^22
        base = w & (NW_ - 1);
        switch (which) {
            case 0:  src = wq; hi = gwq_hi; lo = gwq_lo; break;
            case 1:  src = wk; hi = gwk_hi; lo = gwk_lo; break;
            case 2:  src = wv; hi = gwv_hi; lo = gwv_lo; break;
            default: src = wo; hi = gwo_hi; lo = gwo_lo; break;
        }
    }
    float4 v = *(const float4*)(src + base);
    uint32_t h01, l01, h23, l23;
    cvt_hilo2(v.x, v.y, h01, l01);
    cvt_hilo2(v.z, v.w, h23, l23);
    *(uint2*)(hi + base) = make_uint2(h01, h23);
    *(uint2*)(lo + base) = make_uint2(l01, l23);
}

// ---------------------------------------------------------------------------
// bf16x3 GEMM, cp.async 3-stage pipeline, 2 CTAs/SM (unchanged from round 7,
// except OP==2 epilogue emits fp16 hi/lo V).
// ---------------------------------------------------------------------------
#define ST_ALO 10240
#define ST_WHI 20480
#define ST_WLO 29184
#define ST_STRIDE 37888
#define GEMM_SMEM (3 * ST_STRIDE)   // 113664

template <int OP>
__global__ void __launch_bounds__(256, 2)
gemm_mma_kernel(float* __restrict__ Cout) {
    extern __shared__ char smem[];
    const uint32_t sb = smem_u32(smem);
    const int tid  = threadIdx.x;
    const int lane = tid & 31;
    const int wid  = tid >> 5;
    const int m0 = blockIdx.y * 128;
    const int n0 = blockIdx.x * 128;
    const int wm = (wid & 1) * 64;
    const int wn = (wid >> 1) * 32;

    const __nv_bfloat16 *Ahi, *Alo, *Whi, *Wlo;
    if      (OP == 0) { Ahi = gx_hi;  Alo = gx_lo;  Whi = gwq_hi; Wlo = gwq_lo; }
    else if (OP == 1) { Ahi = gx_hi;  Alo = gx_lo;  Whi = gwk_hi; Wlo = gwk_lo; }
    else if (OP == 2) { Ahi = gx_hi;  Alo = gx_lo;  Whi = gwv_hi; Wlo = gwv_lo; }
    else              { Ahi = gao_hi; Alo = gao_lo; Whi = gwo_hi; Wlo = gwo_lo; }

    float acc[4][4][4];
#pragma unroll
    for (int mt = 0; mt < 4; mt++)
#pragma unroll
        for (int nt = 0; nt < 4; nt++)
#pragma unroll
            for (int f = 0; f < 4; f++) acc[mt][nt][f] = 0.0f;

    const uint32_t a_frag = (wm + (lane & 15)) * 80 + (lane >> 4) * 16;
    const uint32_t b_frag = (lane & 15) * 272 + wn * 2 + (lane >> 4) * 16;

    auto issue = [&](int s) {
        const int k0 = s * 32;
        const uint32_t st = sb + (s % 3) * ST_STRIDE;
#pragma unroll
        for (int i = 0; i < 2; i++) {
            int c = tid + i * 256;
            int row = c >> 2, cc = c & 3;
            size_t g = (size_t)(m0 + row) * 2048 + k0 + cc * 8;
            uint32_t d = st + row * 80 + cc * 16;
            cp16(d, Ahi + g);
            cp16(d + ST_ALO, Alo + g);
        }
#pragma unroll
        for (int i = 0; i < 2; i++) {
            int c = tid + i * 256;
            int row = c >> 4, cc = c & 15;
            size_t g = (size_t)(k0 + row) * 2048 + n0 + cc * 8;
            uint32_t d = st + ST_WHI + row * 272 + cc * 16;
            cp16(d, Whi + g);
            cp16(d + (ST_WLO - ST_WHI), Wlo + g);
        }
    };

    issue(0); cp_commit();
    issue(1); cp_commit();

    const int NS = 64;
    for (int s = 0; s < NS; s++) {
        if (s + 2 < NS) issue(s + 2);
        cp_commit();
        cp_wait<2>();
        __syncthreads();

        const uint32_t base = sb + (s % 3) * ST_STRIDE;
        const uint32_t ahi = base;
        const uint32_t alo = base + ST_ALO;
        const uint32_t whi = base + ST_WHI;
        const uint32_t wlo = base + ST_WLO;

#pragma unroll
        for (int ks = 0; ks < 2; ks++) {
            uint32_t ah[4][4], al[4][4];
#pragma unroll
            for (int mt = 0; mt < 4; mt++) {
                uint32_t ao = a_frag + mt * 1280 + ks * 32;
                ldsm_x4(ah[mt], ahi + ao);
                ldsm_x4(al[mt], alo + ao);
            }
            uint32_t bh[2][4], bl[2][4];
#pragma unroll
            for (int np = 0; np < 2; np++) {
                uint32_t bo = b_frag + ks * 4352 + np * 32;
                ldsm_x4_t(bh[np], whi + bo);
                ldsm_x4_t(bl[np], wlo + bo);
            }
#pragma unroll
            for (int mt = 0; mt < 4; mt++)
#pragma unroll
                for (int nt = 0; nt < 4; nt++)
                    mma_bf16(acc[mt][nt], ah[mt], &bh[nt >> 1][(nt & 1) * 2]);
#pragma unroll
            for (int mt = 0; mt < 4; mt++)
#pragma unroll
                for (int nt = 0; nt < 4; nt++)
                    mma_bf16(acc[mt][nt], ah[mt], &bl[nt >> 1][(nt & 1) * 2]);
#pragma unroll
            for (int mt = 0; mt < 4; mt++)
#pragma unroll
                for (int nt = 0; nt < 4; nt++)
                    mma_bf16(acc[mt][nt], al[mt], &bh[nt >> 1][(nt & 1) * 2]);
        }
        __syncthreads();
    }

    // ---- epilogue ----
    const int lrow = lane >> 2;
    const int lcol = (lane & 3) * 2;
    const int h = blockIdx.x;
    const float QS = 0.0883883476483184405f * 1.4426950408889634f;

#pragma unroll
    for (int mt = 0; mt < 4; mt++) {
#pragma unroll
        for (int rh = 0; rh < 2; rh++) {
            const int m = m0 + wm + mt * 16 + lrow + rh * 8;
            if (OP == 3) {
                float* dst = Cout + (size_t)m * ND_ + n0;
#pragma unroll
                for (int nt = 0; nt < 4; nt++) {
                    int d = wn + nt * 8 + lcol;
                    *(float2*)(dst + d) = make_float2(acc[mt][nt][rh * 2 + 0],
                                                      acc[mt][nt][rh * 2 + 1]);
                }
            } else {
                const int b = m >> 11;
                const int t = m & (T_ - 1);
                const size_t rowoff = (((size_t)(b * H_ + h) * T_ + t) << 7);
                if (OP == 2) {
                    __half* dhi = gv_hi + rowoff;
                    __half* dlo = gv_lo + rowoff;
#pragma unroll
                    for (int nt = 0; nt < 4; nt++) {
                        int d = wn + nt * 8 + lcol;
                        uint32_t hh, ll;
                        cvt_hilo2_f16(acc[mt][nt][rh * 2 + 0], acc[mt][nt][rh * 2 + 1], hh, ll);
                        *(uint32_t*)(dhi + d) = hh;
                        *(uint32_t*)(dlo + d) = ll;
                    }
                } else {
                    __nv_bfloat16* dhi = (OP == 0) ? gq_hi + rowoff : gk_hi + rowoff;
                    __nv_bfloat16* dlo = (OP == 0) ? gq_lo + rowoff : gk_lo + rowoff;
#pragma unroll
                    for (int nt = 0; nt < 4; nt++) {
                        int d = wn + nt * 8 + lcol;
                        float x0 = acc[mt][nt][rh * 2 + 0];
                        float x1 = acc[mt][nt][rh * 2 + 1];
                        float cs = g_cos[t * 64 + (d >> 1)];
                        float sn = g_sin[t * 64 + (d >> 1)];
                        float r0 = x0 * cs - x1 * sn;
                        float r1 = x0 * sn + x1 * cs;
                        if (OP == 0) { r0 *= QS; r1 *= QS; }
                        uint32_t hh, ll;
                        cvt_hilo2(r0, r1, hh, ll);
                        *(uint32_t*)(dhi + d) = hh;
                        *(uint32_t*)(dlo + d) = ll;
                    }
                }
            }
        }
    }
}

// ---------------------------------------------------------------------------
// Tensor-core flash attention: bf16x3 S, fp16 2-term PV (V exact, P fp16).
// Heavy-first q-tile remap; warps skip fully-masked diagonal tiles.
// ---------------------------------------------------------------------------
#define AQ_LO 34816
#define KV_OFF 69632
#define KV_STRIDE 69632
#define KV_KLO 17408
#define KV_VHI 34816
#define KV_VLO 52224
#define ATT_SMEM 208896

__global__ void __launch_bounds__(256, 1) attn_mma_kernel() {
    extern __shared__ char smc[];
    const uint32_t sb = smem_u32(smc);
    const int tid  = threadIdx.x;
    const int lane = tid & 31;
    const int wid  = tid >> 5;
    const int bh   = blockIdx.y;
    const int b    = bh >> 4;
    const int h    = bh & (H_ - 1);
    const int qt   = (int)(gridDim.x - 1) - blockIdx.x;   // heavy tiles first
    const int q0   = qt * 128;
    const int wm   = wid * 16;
    const int lrow = lane >> 2;
    const int lcol2 = (lane & 3) * 2;

    const __nv_bfloat16* qhi = gq_hi + (size_t)bh * T_ * D_;
    const __nv_bfloat16* qlo = gq_lo + (size_t)bh * T_ * D_;
    const __nv_bfloat16* khi = gk_hi + (size_t)bh * T_ * D_;
    const __nv_bfloat16* klo = gk_lo + (size_t)bh * T_ * D_;
    const __half*        vhi = gv_hi + (size_t)bh * T_ * D_;
    const __half*        vlo = gv_lo + (size_t)bh * T_ * D_;

    // ---- issue Q load (group 0) ----
#pragma unroll
    for (int i = 0; i < 8; i++) {
        int c = tid + i * 256;
        int row = c >> 4, cc = c & 15;
        size_t g = (size_t)(q0 + row) * 128 + cc * 8;
        uint32_t d = sb + row * 272 + cc * 16;
        cp16(d, qhi + g);
        cp16(d + AQ_LO, qlo + g);
    }
    cp_commit();

    auto issue_kv = [&](int buf, int k0) {
        uint32_t base = sb + KV_OFF + buf * KV_STRIDE;
#pragma unroll
        for (int i = 0; i < 4; i++) {
            int c = tid + i * 256;
            int row = c >> 4, cc = c & 15;
            size_t g = (size_t)(k0 + row) * 128 + cc * 8;
            uint32_t d = base + row * 272 + cc * 16;
            cp16(d, khi + g);
            cp16(d + KV_KLO, klo + g);
            cp16(d + KV_VHI, vhi + g);
            cp16(d + KV_VLO, vlo + g);
        }
    };

    issue_kv(0, 0);
    cp_commit();

    const uint32_t aq_frag = (wm + (lane & 15)) * 272 + (lane >> 4) * 16;
    const int kb_row = (lane & 7) + ((lane >> 4) << 3);
    const uint32_t kb_frag = kb_row * 272 + ((lane >> 3) & 1) * 16;
    const uint32_t vb_frag = (lane & 15) * 272 + (lane >> 4) * 16;

    float o[16][4];
#pragma unroll
    for (int dt = 0; dt < 16; dt++)
#pragma unroll
        for (int f = 0; f < 4; f++) o[dt][f] = 0.0f;
    float m0 = -1e30f, m1 = -1e30f, l0 = 0.0f, l1 = 0.0f;

    const int njt = 2 * qt + 2;

    for (int jt = 0; jt < njt; jt++) {
        if (jt + 1 < njt) issue_kv((jt + 1) & 1, (jt + 1) * 64);
        cp_commit();
        cp_wait<1>();
        __syncthreads();

        const int k0 = jt * 64;
        // warp-level skip: k-tile entirely above this warp's 16 rows
        if (k0 <= q0 + wm + 15) {
            const uint32_t kvb = sb + KV_OFF + (jt & 1) * KV_STRIDE;
            const uint32_t aqh = sb + aq_frag;
            const uint32_t kbh = kvb + kb_frag;
            const uint32_t vbh = kvb + KV_VHI + vb_frag;

            // ---- S = Q K^T (bf16x3) ----
            float s[8][4];
#pragma unroll
            for (int nt = 0; nt < 8; nt++)
#pragma unroll
                for (int f = 0; f < 4; f++) s[nt][f] = 0.0f;

#pragma unroll
            for (int ks = 0; ks < 8; ks++) {
                uint32_t ah[4], al[4];
                ldsm_x4(ah, aqh + ks * 32);
                ldsm_x4(al, aqh + AQ_LO + ks * 32);
                uint32_t kh[4][4], kl[4][4];
#pragma unroll
                for (int np = 0; np < 4; np++) {
                    uint32_t off = np * 4352 + ks * 32;
                    ldsm_x4(kh[np], kbh + off);
                    ldsm_x4(kl[np], kbh + KV_KLO + off);
                }
#pragma unroll
                for (int np = 0; np < 4; np++) {
                    mma_bf16(s[2 * np],     ah, kh[np]);
                    mma_bf16(s[2 * np + 1], ah, kh[np] + 2);
                }
#pragma unroll
                for (int np = 0; np < 4; np++) {
                    mma_bf16(s[2 * np],     ah, kl[np]);
                    mma_bf16(s[2 * np + 1], ah, kl[np] + 2);
                }
#pragma unroll
                for (int np = 0; np < 4; np++) {
                    mma_bf16(s[2 * np],     al, kh[np]);
                    mma_bf16(s[2 * np + 1], al, kh[np] + 2);
                }
            }

            // ---- causal mask (diagonal tiles only) ----
            if (k0 + 63 > q0 + wm) {
                const int row0 = q0 + wm + lrow;
                const int row1 = row0 + 8;
#pragma unroll
                for (int nt = 0; nt < 8; nt++) {
                    int c0 = k0 + nt * 8 + lcol2;
                    if (c0 > row0)     s[nt][0] = -1e30f;
                    if (c0 + 1 > row0) s[nt][1] = -1e30f;
                    if (c0 > row1)     s[nt][2] = -1e30f;
                    if (c0 + 1 > row1) s[nt][3] = -1e30f;
                }
            }

            // ---- online softmax (base 2) ----
            float mx0 = -1e30f, mx1 = -1e30f;
#pragma unroll
            for (int nt = 0; nt < 8; nt++) {
                mx0 = fmaxf(mx0, fmaxf(s[nt][0], s[nt][1]));
                mx1 = fmaxf(mx1, fmaxf(s[nt][2], s[nt][3]));
            }
            mx0 = fmaxf(mx0, __shfl_xor_sync(0xffffffffu, mx0, 1));
            mx0 = fmaxf(mx0, __shfl_xor_sync(0xffffffffu, mx0, 2));
            mx1 = fmaxf(mx1, __shfl_xor_sync(0xffffffffu, mx1, 1));
            mx1 = fmaxf(mx1, __shfl_xor_sync(0xffffffffu, mx1, 2));
            float m0n = fmaxf(m0, mx0);
            float m1n = fmaxf(m1, mx1);
            float corr0 = exp2p(m0 - m0n);
            float corr1 = exp2p(m1 - m1n);
            m0 = m0n; m1 = m1n;

            uint32_t ph01[8], ph23[8];
            float sum0 = 0.0f, sum1 = 0.0f;
#pragma unroll
            for (int nt = 0; nt < 8; nt++) {
                float p0 = exp2p(s[nt][0] - m0);
                float p1 = exp2p(s[nt][1] - m0);
                float p2 = exp2p(s[nt][2] - m1);
                float p3 = exp2p(s[nt][3] - m1);
                sum0 += p0 + p1;
                sum1 += p2 + p3;
                ph01[nt] = pack_f16x2(p0, p1);
                ph23[nt] = pack_f16x2(p2, p3);
            }
            sum0 += __shfl_xor_sync(0xffffffffu, sum0, 1);
            sum0 += __shfl_xor_sync(0xffffffffu, sum0, 2);
            sum1 += __shfl_xor_sync(0xffffffffu, sum1, 1);
            sum1 += __shfl_xor_sync(0xffffffffu, sum1, 2);
            l0 = l0 * corr0 + sum0;
            l1 = l1 * corr1 + sum1;

#pragma unroll
            for (int dt = 0; dt < 16; dt++) {
                o[dt][0] *= corr0; o[dt][1] *= corr0;
                o[dt][2] *= corr1; o[dt][3] *= corr1;
            }

            // ---- O += P V (fp16 2-term: P*Vhi + P*Vlo; V exact, P fp16) ----
#pragma unroll
            for (int ks = 0; ks < 4; ks++) {
                uint32_t aph[4] = { ph01[2 * ks], ph23[2 * ks],
                                    ph01[2 * ks + 1], ph23[2 * ks + 1] };
#pragma unroll
                for (int half = 0; half < 2; half++) {
                    uint32_t vh[4][4], vl[4][4];
#pragma unroll
                    for (int j = 0; j < 4; j++) {
                        int np = half * 4 + j;
                        uint32_t off = ks * 4352 + np * 32;
                        ldsm_x4_t(vh[j], vbh + off);
                        ldsm_x4_t(vl[j], vbh + (KV_VLO - KV_VHI) + off);
                    }
#pragma unroll
                    for (int j = 0; j < 4; j++) {
                        int np = half * 4 + j;
                        mma_f16(o[2 * np],     aph, vh[j]);
                        mma_f16(o[2 * np + 1], aph, vh[j] + 2);
                    }
#pragma unroll
                    for (int j = 0; j < 4; j++) {
                        int np = half * 4 + j;
                        mma_f16(o[2 * np],     aph, vl[j]);
                        mma_f16(o[2 * np + 1], aph, vl[j] + 2);
                    }
                }
            }
        }
        __syncthreads();
    }

    // ---- epilogue: normalize, split hi/lo, store to gao ----
    const float inv0 = 1.0f / l0;
    const float inv1 = 1.0f / l1;
    const int row0 = q0 + wm + lrow;
    const int row1 = row0 + 8;
    const size_t o0 = (size_t)(b * T_ + row0) * C_ + h * D_;
    const size_t o1 = (size_t)(b * T_ + row1) * C_ + h * D_;
#pragma unroll
    for (int dt = 0; dt < 16; dt++) {
        int d = dt * 8 + lcol2;
        uint32_t hh, ll;
        cvt_hilo2(o[dt][0] * inv0, o[dt][1] * inv0, hh, ll);
        *(uint32_t*)(gao_hi + o0 + d) = hh;
        *(uint32_t*)(gao_lo + o0 + d) = ll;
        cvt_hilo2(o[dt][2] * inv1, o[dt][3] * inv1, hh, ll);
        *(uint32_t*)(gao_hi + o1 + d) = hh;
        *(uint32_t*)(gao_lo + o1 + d) = ll;
    }
}

// ---------------------------------------------------------------------------
// Launch
// ---------------------------------------------------------------------------
extern "C" void kernel_launch(void* const* d_in, const int* in_sizes, int n_in,
                              void* d_out, int out_size) {
    const float* x  = (const float*)d_in[0];
    const float* wq = (const float*)d_in[2];
    const float* wk = (const float*)d_in[3];
    const float* wv = (const float*)d_in[4];
    const float* wo = (const float*)d_in[5];
    float* out = (float*)d_out;

    rope_table_kernel<<<(T_ * (D_ / 2) + 255) / 256, 256>>>();

    const size_t total = NX_ + 4 * NW_;               // 25165824 elements
    split_all_kernel<<<(unsigned)(total / 1024), 256>>>(x, wq, wk, wv, wo);

    cudaFuncSetAttribute(gemm_mma_kernel<0>, cudaFuncAttributeMaxDynamicSharedMemorySize, GEMM_SMEM);
    cudaFuncSetAttribute(gemm_mma_kernel<1>, cudaFuncAttributeMaxDynamicSharedMemorySize, GEMM_SMEM);
    cudaFuncSetAttribute(gemm_mma_kernel<2>, cudaFuncAttributeMaxDynamicSharedMemorySize, GEMM_SMEM);
    cudaFuncSetAttribute(gemm_mma_kernel<3>, cudaFuncAttributeMaxDynamicSharedMemorySize, GEMM_SMEM);
    cudaFuncSetAttribute(attn_mma_kernel,    cudaFuncAttributeMaxDynamicSharedMemorySize, ATT_SMEM);

    dim3 gg(ND_ / 128, M_ / 128);  // (16, 32)
    gemm_mma_kernel<0><<<gg, 256, GEMM_SMEM>>>(nullptr);
    gemm_mma_kernel<1><<<gg, 256, GEMM_SMEM>>>(nullptr);
    gemm_mma_kernel<2><<<gg, 256, GEMM_SMEM>>>(nullptr);

    attn_mma_kernel<<<dim3(T_ / 128, B_ * H_), 256, ATT_SMEM>>>();

    gemm_mma_kernel<3><<<gg, 256, GEMM_SMEM>>>(out);
}

// round 9
// speedup vs baseline: 3.6197x; 1.0021x over previous
#include <cuda_runtime.h>
#include <cuda_bf16.h>
#include <cuda_fp16.h>
#include <math.h>
#include <stdint.h>

// Problem constants
#define B_ 2
#define T_ 2048
#define C_ 2048
#define H_ 16
#define D_ 128
#define M_ (B_ * T_)
#define ND_ (H_ * D_)
#define NX_ ((size_t)M_ * C_)
#define NW_ ((size_t)C_ * ND_)

// ---------------------------------------------------------------------------
// Scratch: bf16 hi/lo pairs (split once, use many times); V in fp16 hi/lo.
// ---------------------------------------------------------------------------
__device__ __nv_bfloat16 gx_hi[NX_],  gx_lo[NX_];
__device__ __nv_bfloat16 gwq_hi[NW_], gwq_lo[NW_];
__device__ __nv_bfloat16 gwk_hi[NW_], gwk_lo[NW_];
__device__ __nv_bfloat16 gwv_hi[NW_], gwv_lo[NW_];
__device__ __nv_bfloat16 gwo_hi[NW_], gwo_lo[NW_];
__device__ __nv_bfloat16 gq_hi[(size_t)B_ * H_ * T_ * D_], gq_lo[(size_t)B_ * H_ * T_ * D_];
__device__ __nv_bfloat16 gk_hi[(size_t)B_ * H_ * T_ * D_], gk_lo[(size_t)B_ * H_ * T_ * D_];
__device__ __half        gv_hi[(size_t)B_ * H_ * T_ * D_], gv_lo[(size_t)B_ * H_ * T_ * D_];
__device__ __nv_bfloat16 gao_hi[NX_], gao_lo[NX_];
__device__ float g_cos[T_ * (D_ / 2)];
__device__ float g_sin[T_ * (D_ / 2)];

// ---------------------------------------------------------------------------
// Helpers
// ---------------------------------------------------------------------------
__device__ __forceinline__ uint32_t smem_u32(const void* p) {
    uint32_t a;
    asm("{ .reg .u64 t; cvta.to.shared.u64 t, %1; cvt.u32.u64 %0, t; }" : "=r"(a) : "l"(p));
    return a;
}
__device__ __forceinline__ void ldsm_x4(uint32_t* r, uint32_t addr) {
    asm volatile("ldmatrix.sync.aligned.m8n8.x4.shared.b16 {%0,%1,%2,%3}, [%4];"
                 : "=r"(r[0]), "=r"(r[1]), "=r"(r[2]), "=r"(r[3]) : "r"(addr));
}
__device__ __forceinline__ void ldsm_x4_t(uint32_t* r, uint32_t addr) {
    asm volatile("ldmatrix.sync.aligned.m8n8.x4.trans.shared.b16 {%0,%1,%2,%3}, [%4];"
                 : "=r"(r[0]), "=r"(r[1]), "=r"(r[2]), "=r"(r[3]) : "r"(addr));
}
__device__ __forceinline__ void mma_bf16(float* c, const uint32_t* a, const uint32_t* b) {
    asm volatile("mma.sync.aligned.m16n8k16.row.col.f32.bf16.bf16.f32 "
                 "{%0,%1,%2,%3}, {%4,%5,%6,%7}, {%8,%9}, {%0,%1,%2,%3};"
                 : "+f"(c[0]), "+f"(c[1]), "+f"(c[2]), "+f"(c[3])
                 : "r"(a[0]), "r"(a[1]), "r"(a[2]), "r"(a[3]), "r"(b[0]), "r"(b[1]));
}
__device__ __forceinline__ void mma_f16(float* c, const uint32_t* a, const uint32_t* b) {
    asm volatile("mma.sync.aligned.m16n8k16.row.col.f32.f16.f16.f32 "
                 "{%0,%1,%2,%3}, {%4,%5,%6,%7}, {%8,%9}, {%0,%1,%2,%3};"
                 : "+f"(c[0]), "+f"(c[1]), "+f"(c[2]), "+f"(c[3])
                 : "r"(a[0]), "r"(a[1]), "r"(a[2]), "r"(a[3]), "r"(b[0]), "r"(b[1]));
}
__device__ __forceinline__ void cvt_hilo2(float x, float y, uint32_t& hi, uint32_t& lo) {
    __nv_bfloat16 hx = __float2bfloat16(x);
    __nv_bfloat16 hy = __float2bfloat16(y);
    __nv_bfloat16 lx = __float2bfloat16(x - __bfloat162float(hx));
    __nv_bfloat16 ly = __float2bfloat16(y - __bfloat162float(hy));
    hi = ((uint32_t)__bfloat16_as_ushort(hy) << 16) | __bfloat16_as_ushort(hx);
    lo = ((uint32_t)__bfloat16_as_ushort(ly) << 16) | __bfloat16_as_ushort(lx);
}
__device__ __forceinline__ void cvt_hilo2_f16(float x, float y, uint32_t& hi, uint32_t& lo) {
    __half hx = __float2half(x);
    __half hy = __float2half(y);
    __half lx = __float2half(x - __half2float(hx));
    __half ly = __float2half(y - __half2float(hy));
    hi = ((uint32_t)__half_as_ushort(hy) << 16) | __half_as_ushort(hx);
    lo = ((uint32_t)__half_as_ushort(ly) << 16) | __half_as_ushort(lx);
}
__device__ __forceinline__ uint32_t pack_f16x2(float lo, float hi) {
    uint32_t r;
    asm("cvt.rn.f16x2.f32 %0, %1, %2;" : "=r"(r) : "f"(hi), "f"(lo));
    return r;
}
__device__ __forceinline__ void cp16(uint32_t dst, const void* src) {
    asm volatile("cp.async.cg.shared.global [%0], [%1], 16;" :: "r"(dst), "l"(src));
}
__device__ __forceinline__ void cp_commit() {
    asm volatile("cp.async.commit_group;" ::: "memory");
}
template <int N>
__device__ __forceinline__ void cp_wait() {
    asm volatile("cp.async.wait_group %0;" :: "n"(N) : "memory");
}
// exp2 on the FMA pipe
__device__ __forceinline__ float exp2p(float t) {
    t = fmaxf(t, -100.0f);
    float nf = rintf(t);
    float f = t - nf;
    float p =             1.3333558146e-3f;
    p = fmaf(p, f, 9.6181291076e-3f);
    p = fmaf(p, f, 5.5504108665e-2f);
    p = fmaf(p, f, 2.4022650696e-1f);
    p = fmaf(p, f, 6.9314718056e-1f);
    p = fmaf(p, f, 1.0f);
    float sc = __int_as_float(((int)nf + 127) << 23);
    return p * sc;
}

// ---------------------------------------------------------------------------
// RoPE table + fused one-time fp32 -> bf16 hi/lo split (single launch)
// ---------------------------------------------------------------------------
__global__ void rope_table_kernel() {
    int i = blockIdx.x * blockDim.x + threadIdx.x;
    if (i >= T_ * (D_ / 2)) return;
    int t  = i >> 6;
    int d2 = i & 63;
    float inv = powf(10000.0f, -((float)(2 * d2)) / (float)D_);
    float ang = (float)t * inv;
    g_cos[i] = cosf(ang);
    g_sin[i] = sinf(ang);
}

__global__ void split_all_kernel(const float* __restrict__ x,
                                 const float* __restrict__ wq,
                                 const float* __restrict__ wk,
                                 const float* __restrict__ wv,
                                 const float* __restrict__ wo) {
    size_t idx = ((size_t)blockIdx.x * blockDim.x + threadIdx.x) * 4;
    const float* src;
    __nv_bfloat16 *hi, *lo;
    size_t base;
    if (idx < NX_) {
        src = x; hi = gx_hi; lo = gx_lo; base = idx;
    } else {
        size_t w = idx - NX_;
        int which = (int)(w >> 22);       // NW_ = 2^22
        base = w & (NW_ - 1);
        switch (which) {
            case 0:  src = wq; hi = gwq_hi; lo = gwq_lo; break;
            case 1:  src = wk; hi = gwk_hi; lo = gwk_lo; break;
            case 2:  src = wv; hi = gwv_hi; lo = gwv_lo; break;
            default: src = wo; hi = gwo_hi; lo = gwo_lo; break;
        }
    }
    float4 v = *(const float4*)(src + base);
    uint32_t h01, l01, h23, l23;
    cvt_hilo2(v.x, v.y, h01, l01);
    cvt_hilo2(v.z, v.w, h23, l23);
    *(uint2*)(hi + base) = make_uint2(h01, h23);
    *(uint2*)(lo + base) = make_uint2(l01, l23);
}

// ---------------------------------------------------------------------------
// bf16x3 GEMM, cp.async 3-stage pipeline, 2 CTAs/SM (unchanged from round 7,
// except OP==2 epilogue emits fp16 hi/lo V).
// ---------------------------------------------------------------------------
#define ST_ALO 10240
#define ST_WHI 20480
#define ST_WLO 29184
#define ST_STRIDE 37888
#define GEMM_SMEM (3 * ST_STRIDE)   // 113664

template <int OP>
__global__ void __launch_bounds__(256, 2)
gemm_mma_kernel(float* __restrict__ Cout) {
    extern __shared__ char smem[];
    const uint32_t sb = smem_u32(smem);
    const int tid  = threadIdx.x;
    const int lane = tid & 31;
    const int wid  = tid >> 5;
    const int m0 = blockIdx.y * 128;
    const int n0 = blockIdx.x * 128;
    const int wm = (wid & 1) * 64;
    const int wn = (wid >> 1) * 32;

    const __nv_bfloat16 *Ahi, *Alo, *Whi, *Wlo;
    if      (OP == 0) { Ahi = gx_hi;  Alo = gx_lo;  Whi = gwq_hi; Wlo = gwq_lo; }
    else if (OP == 1) { Ahi = gx_hi;  Alo = gx_lo;  Whi = gwk_hi; Wlo = gwk_lo; }
    else if (OP == 2) { Ahi = gx_hi;  Alo = gx_lo;  Whi = gwv_hi; Wlo = gwv_lo; }
    else              { Ahi = gao_hi; Alo = gao_lo; Whi = gwo_hi; Wlo = gwo_lo; }

    float acc[4][4][4];
#pragma unroll
    for (int mt = 0; mt < 4; mt++)
#pragma unroll
        for (int nt = 0; nt < 4; nt++)
#pragma unroll
            for (int f = 0; f < 4; f++) acc[mt][nt][f] = 0.0f;

    const uint32_t a_frag = (wm + (lane & 15)) * 80 + (lane >> 4) * 16;
    const uint32_t b_frag = (lane & 15) * 272 + wn * 2 + (lane >> 4) * 16;

    auto issue = [&](int s) {
        const int k0 = s * 32;
        const uint32_t st = sb + (s % 3) * ST_STRIDE;
#pragma unroll
        for (int i = 0; i < 2; i++) {
            int c = tid + i * 256;
            int row = c >> 2, cc = c & 3;
            size_t g = (size_t)(m0 + row) * 2048 + k0 + cc * 8;
            uint32_t d = st + row * 80 + cc * 16;
            cp16(d, Ahi + g);
            cp16(d + ST_ALO, Alo + g);
        }
#pragma unroll
        for (int i = 0; i < 2; i++) {
            int c = tid + i * 256;
            int row = c >> 4, cc = c & 15;
            size_t g = (size_t)(k0 + row) * 2048 + n0 + cc * 8;
            uint32_t d = st + ST_WHI + row * 272 + cc * 16;
            cp16(d, Whi + g);
            cp16(d + (ST_WLO - ST_WHI), Wlo + g);
        }
    };

    issue(0); cp_commit();
    issue(1); cp_commit();

    const int NS = 64;
    for (int s = 0; s < NS; s++) {
        if (s + 2 < NS) issue(s + 2);
        cp_commit();
        cp_wait<2>();
        __syncthreads();

        const uint32_t base = sb + (s % 3) * ST_STRIDE;
        const uint32_t ahi = base;
        const uint32_t alo = base + ST_ALO;
        const uint32_t whi = base + ST_WHI;
        const uint32_t wlo = base + ST_WLO;

#pragma unroll
        for (int ks = 0; ks < 2; ks++) {
            uint32_t ah[4][4], al[4][4];
#pragma unroll
            for (int mt = 0; mt < 4; mt++) {
                uint32_t ao = a_frag + mt * 1280 + ks * 32;
                ldsm_x4(ah[mt], ahi + ao);
                ldsm_x4(al[mt], alo + ao);
            }
            uint32_t bh[2][4], bl[2][4];
#pragma unroll
            for (int np = 0; np < 2; np++) {
                uint32_t bo = b_frag + ks * 4352 + np * 32;
                ldsm_x4_t(bh[np], whi + bo);
                ldsm_x4_t(bl[np], wlo + bo);
            }
#pragma unroll
            for (int mt = 0; mt < 4; mt++)
#pragma unroll
                for (int nt = 0; nt < 4; nt++)
                    mma_bf16(acc[mt][nt], ah[mt], &bh[nt >> 1][(nt & 1) * 2]);
#pragma unroll
            for (int mt = 0; mt < 4; mt++)
#pragma unroll
                for (int nt = 0; nt < 4; nt++)
                    mma_bf16(acc[mt][nt], ah[mt], &bl[nt >> 1][(nt & 1) * 2]);
#pragma unroll
            for (int mt = 0; mt < 4; mt++)
#pragma unroll
                for (int nt = 0; nt < 4; nt++)
                    mma_bf16(acc[mt][nt], al[mt], &bh[nt >> 1][(nt & 1) * 2]);
        }
        __syncthreads();
    }

    // ---- epilogue ----
    const int lrow = lane >> 2;
    const int lcol = (lane & 3) * 2;
    const int h = blockIdx.x;
    const float QS = 0.0883883476483184405f * 1.4426950408889634f;

#pragma unroll
    for (int mt = 0; mt < 4; mt++) {
#pragma unroll
        for (int rh = 0; rh < 2; rh++) {
            const int m = m0 + wm + mt * 16 + lrow + rh * 8;
            if (OP == 3) {
                float* dst = Cout + (size_t)m * ND_ + n0;
#pragma unroll
                for (int nt = 0; nt < 4; nt++) {
                    int d = wn + nt * 8 + lcol;
                    *(float2*)(dst + d) = make_float2(acc[mt][nt][rh * 2 + 0],
                                                      acc[mt][nt][rh * 2 + 1]);
                }
            } else {
                const int b = m >> 11;
                const int t = m & (T_ - 1);
                const size_t rowoff = (((size_t)(b * H_ + h) * T_ + t) << 7);
                if (OP == 2) {
                    __half* dhi = gv_hi + rowoff;
                    __half* dlo = gv_lo + rowoff;
#pragma unroll
                    for (int nt = 0; nt < 4; nt++) {
                        int d = wn + nt * 8 + lcol;
                        uint32_t hh, ll;
                        cvt_hilo2_f16(acc[mt][nt][rh * 2 + 0], acc[mt][nt][rh * 2 + 1], hh, ll);
                        *(uint32_t*)(dhi + d) = hh;
                        *(uint32_t*)(dlo + d) = ll;
                    }
                } else {
                    __nv_bfloat16* dhi = (OP == 0) ? gq_hi + rowoff : gk_hi + rowoff;
                    __nv_bfloat16* dlo = (OP == 0) ? gq_lo + rowoff : gk_lo + rowoff;
#pragma unroll
                    for (int nt = 0; nt < 4; nt++) {
                        int d = wn + nt * 8 + lcol;
                        float x0 = acc[mt][nt][rh * 2 + 0];
                        float x1 = acc[mt][nt][rh * 2 + 1];
                        float cs = g_cos[t * 64 + (d >> 1)];
                        float sn = g_sin[t * 64 + (d >> 1)];
                        float r0 = x0 * cs - x1 * sn;
                        float r1 = x0 * sn + x1 * cs;
                        if (OP == 0) { r0 *= QS; r1 *= QS; }
                        uint32_t hh, ll;
                        cvt_hilo2(r0, r1, hh, ll);
                        *(uint32_t*)(dhi + d) = hh;
                        *(uint32_t*)(dlo + d) = ll;
                    }
                }
            }
        }
    }
}

// ---------------------------------------------------------------------------
// Tensor-core flash attention: bf16x3 S, fp16 2-term PV (V exact, P fp16).
// Heavy-first q-tile remap; warps skip fully-masked diagonal tiles.
// ---------------------------------------------------------------------------
#define AQ_LO 34816
#define KV_OFF 69632
#define KV_STRIDE 69632
#define KV_KLO 17408
#define KV_VHI 34816
#define KV_VLO 52224
#define ATT_SMEM 208896

__global__ void __launch_bounds__(256, 1) attn_mma_kernel() {
    extern __shared__ char smc[];
    const uint32_t sb = smem_u32(smc);
    const int tid  = threadIdx.x;
    const int lane = tid & 31;
    const int wid  = tid >> 5;
    const int bh   = blockIdx.y;
    const int b    = bh >> 4;
    const int h    = bh & (H_ - 1);
    const int qt   = (int)(gridDim.x - 1) - blockIdx.x;   // heavy tiles first
    const int q0   = qt * 128;
    const int wm   = wid * 16;
    const int lrow = lane >> 2;
    const int lcol2 = (lane & 3) * 2;

    const __nv_bfloat16* qhi = gq_hi + (size_t)bh * T_ * D_;
    const __nv_bfloat16* qlo = gq_lo + (size_t)bh * T_ * D_;
    const __nv_bfloat16* khi = gk_hi + (size_t)bh * T_ * D_;
    const __nv_bfloat16* klo = gk_lo + (size_t)bh * T_ * D_;
    const __half*        vhi = gv_hi + (size_t)bh * T_ * D_;
    const __half*        vlo = gv_lo + (size_t)bh * T_ * D_;

    // ---- issue Q load (group 0) ----
#pragma unroll
    for (int i = 0; i < 8; i++) {
        int c = tid + i * 256;
        int row = c >> 4, cc = c & 15;
        size_t g = (size_t)(q0 + row) * 128 + cc * 8;
        uint32_t d = sb + row * 272 + cc * 16;
        cp16(d, qhi + g);
        cp16(d + AQ_LO, qlo + g);
    }
    cp_commit();

    auto issue_kv = [&](int buf, int k0) {
        uint32_t base = sb + KV_OFF + buf * KV_STRIDE;
#pragma unroll
        for (int i = 0; i < 4; i++) {
            int c = tid + i * 256;
            int row = c >> 4, cc = c & 15;
            size_t g = (size_t)(k0 + row) * 128 + cc * 8;
            uint32_t d = base + row * 272 + cc * 16;
            cp16(d, khi + g);
            cp16(d + KV_KLO, klo + g);
            cp16(d + KV_VHI, vhi + g);
            cp16(d + KV_VLO, vlo + g);
        }
    };

    issue_kv(0, 0);
    cp_commit();

    const uint32_t aq_frag = (wm + (lane & 15)) * 272 + (lane >> 4) * 16;
    const int kb_row = (lane & 7) + ((lane >> 4) << 3);
    const uint32_t kb_frag = kb_row * 272 + ((lane >> 3) & 1) * 16;
    const uint32_t vb_frag = (lane & 15) * 272 + (lane >> 4) * 16;

    float o[16][4];
#pragma unroll
    for (int dt = 0; dt < 16; dt++)
#pragma unroll
        for (int f = 0; f < 4; f++) o[dt][f] = 0.0f;
    float m0 = -1e30f, m1 = -1e30f, l0 = 0.0f, l1 = 0.0f;

    const int njt = 2 * qt + 2;

    for (int jt = 0; jt < njt; jt++) {
        if (jt + 1 < njt) issue_kv((jt + 1) & 1, (jt + 1) * 64);
        cp_commit();
        cp_wait<1>();
        __syncthreads();

        const int k0 = jt * 64;
        // warp-level skip: k-tile entirely above this warp's 16 rows
        if (k0 <= q0 + wm + 15) {
            const uint32_t kvb = sb + KV_OFF + (jt & 1) * KV_STRIDE;
            const uint32_t aqh = sb + aq_frag;
            const uint32_t kbh = kvb + kb_frag;
            const uint32_t vbh = kvb + KV_VHI + vb_frag;

            // ---- S = Q K^T (bf16x3) ----
            float s[8][4];
#pragma unroll
            for (int nt = 0; nt < 8; nt++)
#pragma unroll
                for (int f = 0; f < 4; f++) s[nt][f] = 0.0f;

#pragma unroll
            for (int ks = 0; ks < 8; ks++) {
                uint32_t ah[4], al[4];
                ldsm_x4(ah, aqh + ks * 32);
                ldsm_x4(al, aqh + AQ_LO + ks * 32);
                uint32_t kh[4][4], kl[4][4];
#pragma unroll
                for (int np = 0; np < 4; np++) {
                    uint32_t off = np * 4352 + ks * 32;
                    ldsm_x4(kh[np], kbh + off);
                    ldsm_x4(kl[np], kbh + KV_KLO + off);
                }
#pragma unroll
                for (int np = 0; np < 4; np++) {
                    mma_bf16(s[2 * np],     ah, kh[np]);
                    mma_bf16(s[2 * np + 1], ah, kh[np] + 2);
                }
#pragma unroll
                for (int np = 0; np < 4; np++) {
                    mma_bf16(s[2 * np],     ah, kl[np]);
                    mma_bf16(s[2 * np + 1], ah, kl[np] + 2);
                }
#pragma unroll
                for (int np = 0; np < 4; np++) {
                    mma_bf16(s[2 * np],     al, kh[np]);
                    mma_bf16(s[2 * np + 1], al, kh[np] + 2);
                }
            }

            // ---- causal mask (diagonal tiles only) ----
            if (k0 + 63 > q0 + wm) {
                const int row0 = q0 + wm + lrow;
                const int row1 = row0 + 8;
#pragma unroll
                for (int nt = 0; nt < 8; nt++) {
                    int c0 = k0 + nt * 8 + lcol2;
                    if (c0 > row0)     s[nt][0] = -1e30f;
                    if (c0 + 1 > row0) s[nt][1] = -1e30f;
                    if (c0 > row1)     s[nt][2] = -1e30f;
                    if (c0 + 1 > row1) s[nt][3] = -1e30f;
                }
            }

            // ---- online softmax (base 2) ----
            float mx0 = -1e30f, mx1 = -1e30f;
#pragma unroll
            for (int nt = 0; nt < 8; nt++) {
                mx0 = fmaxf(mx0, fmaxf(s[nt][0], s[nt][1]));
                mx1 = fmaxf(mx1, fmaxf(s[nt][2], s[nt][3]));
            }
            mx0 = fmaxf(mx0, __shfl_xor_sync(0xffffffffu, mx0, 1));
            mx0 = fmaxf(mx0, __shfl_xor_sync(0xffffffffu, mx0, 2));
            mx1 = fmaxf(mx1, __shfl_xor_sync(0xffffffffu, mx1, 1));
            mx1 = fmaxf(mx1, __shfl_xor_sync(0xffffffffu, mx1, 2));
            float m0n = fmaxf(m0, mx0);
            float m1n = fmaxf(m1, mx1);
            float corr0 = exp2p(m0 - m0n);
            float corr1 = exp2p(m1 - m1n);
            m0 = m0n; m1 = m1n;

            uint32_t ph01[8], ph23[8];
            float sum0 = 0.0f, sum1 = 0.0f;
#pragma unroll
            for (int nt = 0; nt < 8; nt++) {
                float p0 = exp2p(s[nt][0] - m0);
                float p1 = exp2p(s[nt][1] - m0);
                float p2 = exp2p(s[nt][2] - m1);
                float p3 = exp2p(s[nt][3] - m1);
                sum0 += p0 + p1;
                sum1 += p2 + p3;
                ph01[nt] = pack_f16x2(p0, p1);
                ph23[nt] = pack_f16x2(p2, p3);
            }
            sum0 += __shfl_xor_sync(0xffffffffu, sum0, 1);
            sum0 += __shfl_xor_sync(0xffffffffu, sum0, 2);
            sum1 += __shfl_xor_sync(0xffffffffu, sum1, 1);
            sum1 += __shfl_xor_sync(0xffffffffu, sum1, 2);
            l0 = l0 * corr0 + sum0;
            l1 = l1 * corr1 + sum1;

#pragma unroll
            for (int dt = 0; dt < 16; dt++) {
                o[dt][0] *= corr0; o[dt][1] *= corr0;
                o[dt][2] *= corr1; o[dt][3] *= corr1;
            }

            // ---- O += P V (fp16 2-term: P*Vhi + P*Vlo; V exact, P fp16) ----
#pragma unroll
            for (int ks = 0; ks < 4; ks++) {
                uint32_t aph[4] = { ph01[2 * ks], ph23[2 * ks],
                                    ph01[2 * ks + 1], ph23[2 * ks + 1] };
#pragma unroll
                for (int half = 0; half < 2; half++) {
                    uint32_t vh[4][4], vl[4][4];
#pragma unroll
                    for (int j = 0; j < 4; j++) {
                        int np = half * 4 + j;
                        uint32_t off = ks * 4352 + np * 32;
                        ldsm_x4_t(vh[j], vbh + off);
                        ldsm_x4_t(vl[j], vbh + (KV_VLO - KV_VHI) + off);
                    }
#pragma unroll
                    for (int j = 0; j < 4; j++) {
                        int np = half * 4 + j;
                        mma_f16(o[2 * np],     aph, vh[j]);
                        mma_f16(o[2 * np + 1], aph, vh[j] + 2);
                    }
#pragma unroll
                    for (int j = 0; j < 4; j++) {
                        int np = half * 4 + j;
                        mma_f16(o[2 * np],     aph, vl[j]);
                        mma_f16(o[2 * np + 1], aph, vl[j] + 2);
                    }
                }
            }
        }
        __syncthreads();
    }

    // ---- epilogue: normalize, split hi/lo, store to gao ----
    const float inv0 = 1.0f / l0;
    const float inv1 = 1.0f / l1;
    const int row0 = q0 + wm + lrow;
    const int row1 = row0 + 8;
    const size_t o0 = (size_t)(b * T_ + row0) * C_ + h * D_;
    const size_t o1 = (size_t)(b * T_ + row1) * C_ + h * D_;
#pragma unroll
    for (int dt = 0; dt < 16; dt++) {
        int d = dt * 8 + lcol2;
        uint32_t hh, ll;
        cvt_hilo2(o[dt][0] * inv0, o[dt][1] * inv0, hh, ll);
        *(uint32_t*)(gao_hi + o0 + d) = hh;
        *(uint32_t*)(gao_lo + o0 + d) = ll;
        cvt_hilo2(o[dt][2] * inv1, o[dt][3] * inv1, hh, ll);
        *(uint32_t*)(gao_hi + o1 + d) = hh;
        *(uint32_t*)(gao_lo + o1 + d) = ll;
    }
}

// ---------------------------------------------------------------------------
// Launch
// ---------------------------------------------------------------------------
extern "C" void kernel_launch(void* const* d_in, const int* in_sizes, int n_in,
                              void* d_out, int out_size) {
    const float* x  = (const float*)d_in[0];
    const float* wq = (const float*)d_in[2];
    const float* wk = (const float*)d_in[3];
    const float* wv = (const float*)d_in[4];
    const float* wo = (const float*)d_in[5];
    float* out = (float*)d_out;

    rope_table_kernel<<<(T_ * (D_ / 2) + 255) / 256, 256>>>();

    const size_t total = NX_ + 4 * NW_;               // 25165824 elements
    split_all_kernel<<<(unsigned)(total / 1024), 256>>>(x, wq, wk, wv, wo);

    cudaFuncSetAttribute(gemm_mma_kernel<0>, cudaFuncAttributeMaxDynamicSharedMemorySize, GEMM_SMEM);
    cudaFuncSetAttribute(gemm_mma_kernel<1>, cudaFuncAttributeMaxDynamicSharedMemorySize, GEMM_SMEM);
    cudaFuncSetAttribute(gemm_mma_kernel<2>, cudaFuncAttributeMaxDynamicSharedMemorySize, GEMM_SMEM);
    cudaFuncSetAttribute(gemm_mma_kernel<3>, cudaFuncAttributeMaxDynamicSharedMemorySize, GEMM_SMEM);
    cudaFuncSetAttribute(attn_mma_kernel,    cudaFuncAttributeMaxDynamicSharedMemorySize, ATT_SMEM);

    dim3 gg(ND_ / 128, M_ / 128);  // (16, 32)
    gemm_mma_kernel<0><<<gg, 256, GEMM_SMEM>>>(nullptr);
    gemm_mma_kernel<1><<<gg, 256, GEMM_SMEM>>>(nullptr);
    gemm_mma_kernel<2><<<gg, 256, GEMM_SMEM>>>(nullptr);

    attn_mma_kernel<<<dim3(T_ / 128, B_ * H_), 256, ATT_SMEM>>>();

    gemm_mma_kernel<3><<<gg, 256, GEMM_SMEM>>>(out);
}